// round 2
// baseline (speedup 1.0000x reference)
#include <cuda_runtime.h>
#include <cuda_bf16.h>
#include <math.h>

// Problem constants
#define BB 32
#define TT 512
#define DD 1024
#define HH 16
#define HD 64
#define MT (BB*TT)          // 16384 rows
#define NKQV (3*DD)         // 3072

// ---------------- scratch (device globals; no cudaMalloc allowed) ----------
__device__ float g_h[(size_t)MT * DD];        // 64 MB  : h = x@Wi + bi
__device__ float g_kqv[(size_t)MT * NKQV];    // 192 MB : [k | q | v] per row
__device__ float g_attn[(size_t)MT * DD];     // 64 MB  : attention output (concat heads)
__device__ float g_wkqv[(size_t)DD * NKQV];   // 12 MB  : repacked [D, 3D] weights
__device__ float g_bkqv[NKQV];

// ---------------- repack Wk/Wq/Wv ([H,D,HD]) -> [D, 3*D] col-concat --------
__global__ void repack_kernel(const float* __restrict__ Wk, const float* __restrict__ bk,
                              const float* __restrict__ Wq, const float* __restrict__ bq,
                              const float* __restrict__ Wv, const float* __restrict__ bv)
{
    int idx = blockIdx.x * blockDim.x + threadIdx.x;
    if (idx < DD * NKQV) {
        int d = idx / NKQV;
        int n = idx - d * NKQV;
        int sec = n >> 10;          // 0=k, 1=q, 2=v
        int m   = n & 1023;         // h*64 + e
        const float* W = (sec == 0) ? Wk : (sec == 1) ? Wq : Wv;
        // W[h][d][e] with h = m>>6, e = m&63
        g_wkqv[idx] = W[(size_t)(m >> 6) * (DD * HD) + (size_t)d * HD + (m & 63)];
    }
    if (idx < NKQV) {
        int sec = idx >> 10;
        int m   = idx & 1023;
        const float* bb = (sec == 0) ? bk : (sec == 1) ? bq : bv;
        g_bkqv[idx] = bb[m];
    }
}

// ---------------- SGEMM: C[M,N] = A[M,K] @ B[K,N] + bias[N] ---------------
// BM=128, BN=64, BK=16; 256 threads (16x16); thread tile 8x4.
#define BM 128
#define BN 64
#define BK 16
#define TM 8
#define TN 4

__global__ __launch_bounds__(256)
void sgemm_bias(const float* __restrict__ A, const float* __restrict__ B,
                const float* __restrict__ bias, float* __restrict__ C,
                int M, int N, int K)
{
    __shared__ float As[BK][BM + 4];   // +4 pad: conflict-free transposed stores, 16B-aligned rows
    __shared__ float Bs[BK][BN];

    const int tid = threadIdx.x;
    const int tx = tid & 15;
    const int ty = tid >> 4;
    const int bm = blockIdx.y * BM;
    const int bn = blockIdx.x * BN;

    const int arow = tid >> 2;       // 0..63
    const int ac4  = tid & 3;        // k-group
    const int brow = tid >> 4;       // 0..15
    const int bc4  = tid & 15;       // n-group

    float acc[TM][TN];
#pragma unroll
    for (int i = 0; i < TM; i++)
#pragma unroll
        for (int j = 0; j < TN; j++) acc[i][j] = 0.f;

    for (int k0 = 0; k0 < K; k0 += BK) {
        // Load A tile (128x16) as float4, store transposed As[k][row]
#pragma unroll
        for (int rep = 0; rep < 2; rep++) {
            int r = arow + rep * 64;
            float4 va = *(const float4*)(A + (size_t)(bm + r) * K + k0 + ac4 * 4);
            As[ac4 * 4 + 0][r] = va.x;
            As[ac4 * 4 + 1][r] = va.y;
            As[ac4 * 4 + 2][r] = va.z;
            As[ac4 * 4 + 3][r] = va.w;
        }
        // Load B tile (16x64) as float4, natural layout
        {
            float4 vb = *(const float4*)(B + (size_t)(k0 + brow) * N + bn + bc4 * 4);
            *(float4*)&Bs[brow][bc4 * 4] = vb;
        }
        __syncthreads();

#pragma unroll
        for (int k = 0; k < BK; k++) {
            float a[TM], b[TN];
#pragma unroll
            for (int i = 0; i < TM; i++) a[i] = As[k][ty * TM + i];
#pragma unroll
            for (int j = 0; j < TN; j++) b[j] = Bs[k][tx * TN + j];
#pragma unroll
            for (int i = 0; i < TM; i++)
#pragma unroll
                for (int j = 0; j < TN; j++) acc[i][j] = fmaf(a[i], b[j], acc[i][j]);
        }
        __syncthreads();
    }

    // Epilogue: add bias, vectorized store
#pragma unroll
    for (int i = 0; i < TM; i++) {
        int row = bm + ty * TM + i;
        int col = bn + tx * TN;
        float4 vo;
        vo.x = acc[i][0] + bias[col + 0];
        vo.y = acc[i][1] + bias[col + 1];
        vo.z = acc[i][2] + bias[col + 2];
        vo.w = acc[i][3] + bias[col + 3];
        *(float4*)(C + (size_t)row * N + col) = vo;
    }
}

// ---------------- fused causal flash attention -----------------------------
// Reference computes wei[t,s] = k_t . q_s, masks s<=t, softmax over s, out = wei@v.
// => standard causal flash attention with Q:=k, K:=q, V:=v, no scale.
// One CTA: (b, h, t-tile of 64 rows). 256 threads (16x16), thread tile 4x4.
// Dynamic smem: Qs[64][65] + Ks[64][65] + Ps[64][65] + Vs[64][64]
#define FLASH_SMEM ((3 * 64 * 65 + 64 * 64) * (int)sizeof(float))

__global__ __launch_bounds__(256)
void flash_kernel(const float* __restrict__ kqv, float* __restrict__ out)
{
    extern __shared__ float sm[];
    float* Qs = sm;                 // [64][65] transposed: Qs[e][i]
    float* Ks = Qs + 64 * 65;       // [64][65] transposed: Ks[e][j]
    float* Ps = Ks + 64 * 65;       // [64][65] transposed: Ps[s][i]
    float* Vs = Ps + 64 * 65;       // [64][64] natural:    Vs[s][e]

    const int tid = threadIdx.x;
    const int tx = tid & 15;
    const int ty = tid >> 4;
    const int tt = blockIdx.x;      // t-tile 0..7
    const int h  = blockIdx.y;      // head
    const int b  = blockIdx.z;      // batch

    const size_t base = (size_t)b * TT * NKQV + (size_t)h * HD;

    // Load Q tile (k-section, offset 0): rows t = tt*64 + i, transposed store
#pragma unroll
    for (int rep = 0; rep < 4; rep++) {
        int i = (tid >> 4) + rep * 16;
        int e = (tid & 15) * 4;
        float4 v = *(const float4*)(kqv + base + (size_t)(tt * 64 + i) * NKQV + e);
        Qs[(e + 0) * 65 + i] = v.x;
        Qs[(e + 1) * 65 + i] = v.y;
        Qs[(e + 2) * 65 + i] = v.z;
        Qs[(e + 3) * 65 + i] = v.w;
    }

    float m_i[4], l_i[4], o[4][4];
#pragma unroll
    for (int i = 0; i < 4; i++) {
        m_i[i] = -1e30f;
        l_i[i] = 0.f;
#pragma unroll
        for (int e = 0; e < 4; e++) o[i][e] = 0.f;
    }

    for (int st = 0; st <= tt; st++) {
        __syncthreads();   // prior iter done reading Ks/Vs/Ps; also covers Qs on st=0

        // Load K tile (q-section, +1024) transposed, and V tile (+2048) natural
#pragma unroll
        for (int rep = 0; rep < 4; rep++) {
            int j = (tid >> 4) + rep * 16;
            int e = (tid & 15) * 4;
            float4 vk = *(const float4*)(kqv + base + 1024 + (size_t)(st * 64 + j) * NKQV + e);
            Ks[(e + 0) * 65 + j] = vk.x;
            Ks[(e + 1) * 65 + j] = vk.y;
            Ks[(e + 2) * 65 + j] = vk.z;
            Ks[(e + 3) * 65 + j] = vk.w;
            float4 vv = *(const float4*)(kqv + base + 2048 + (size_t)(st * 64 + j) * NKQV + e);
            *(float4*)&Vs[j * 64 + e] = vv;
        }
        __syncthreads();

        // S = Q @ K^T  (4x4 per thread over 64-deep dot)
        float s_acc[4][4];
#pragma unroll
        for (int i = 0; i < 4; i++)
#pragma unroll
            for (int j = 0; j < 4; j++) s_acc[i][j] = 0.f;

#pragma unroll 8
        for (int e = 0; e < 64; e++) {
            float a[4], bq[4];
#pragma unroll
            for (int i = 0; i < 4; i++) a[i] = Qs[e * 65 + ty * 4 + i];
#pragma unroll
            for (int j = 0; j < 4; j++) bq[j] = Ks[e * 65 + tx * 4 + j];
#pragma unroll
            for (int i = 0; i < 4; i++)
#pragma unroll
                for (int j = 0; j < 4; j++) s_acc[i][j] = fmaf(a[i], bq[j], s_acc[i][j]);
        }

        // Causal mask on diagonal tile: col (s) > row (t) -> -inf
        if (st == tt) {
#pragma unroll
            for (int i = 0; i < 4; i++)
#pragma unroll
                for (int j = 0; j < 4; j++)
                    if (tx * 4 + j > ty * 4 + i) s_acc[i][j] = -1e30f;
        }

        // Online softmax: each row spans the 16 tx-threads (aligned 16-lane groups)
#pragma unroll
        for (int i = 0; i < 4; i++) {
            float mx = s_acc[i][0];
            mx = fmaxf(mx, s_acc[i][1]);
            mx = fmaxf(mx, s_acc[i][2]);
            mx = fmaxf(mx, s_acc[i][3]);
#pragma unroll
            for (int off = 1; off < 16; off <<= 1)
                mx = fmaxf(mx, __shfl_xor_sync(0xffffffffu, mx, off, 16));
            float m_new = fmaxf(m_i[i], mx);
            float scale = __expf(m_i[i] - m_new);
            float lsum = 0.f;
#pragma unroll
            for (int j = 0; j < 4; j++) {
                float p = __expf(s_acc[i][j] - m_new);
                s_acc[i][j] = p;
                lsum += p;
            }
#pragma unroll
            for (int off = 1; off < 16; off <<= 1)
                lsum += __shfl_xor_sync(0xffffffffu, lsum, off, 16);
            l_i[i] = l_i[i] * scale + lsum;
            m_i[i] = m_new;
#pragma unroll
            for (int e = 0; e < 4; e++) o[i][e] *= scale;
        }

        // P -> smem (transposed: Ps[s][i])
#pragma unroll
        for (int i = 0; i < 4; i++)
#pragma unroll
            for (int j = 0; j < 4; j++)
                Ps[(tx * 4 + j) * 65 + ty * 4 + i] = s_acc[i][j];
        __syncthreads();

        // O += P @ V
#pragma unroll 8
        for (int s = 0; s < 64; s++) {
            float a[4], bv[4];
#pragma unroll
            for (int i = 0; i < 4; i++) a[i] = Ps[s * 65 + ty * 4 + i];
#pragma unroll
            for (int e = 0; e < 4; e++) bv[e] = Vs[s * 64 + tx * 4 + e];
#pragma unroll
            for (int i = 0; i < 4; i++)
#pragma unroll
                for (int e = 0; e < 4; e++) o[i][e] = fmaf(a[i], bv[e], o[i][e]);
        }
    }

    // Epilogue: normalize and write concat-head layout [b*T+t, h*64+e]
#pragma unroll
    for (int i = 0; i < 4; i++) {
        float inv = 1.f / l_i[i];
        int t_g = tt * 64 + ty * 4 + i;
        float4 vo;
        vo.x = o[i][0] * inv;
        vo.y = o[i][1] * inv;
        vo.z = o[i][2] * inv;
        vo.w = o[i][3] * inv;
        *(float4*)(out + (size_t)(b * TT + t_g) * DD + h * HD + tx * 4) = vo;
    }
}

// ---------------- launch ---------------------------------------------------
extern "C" void kernel_launch(void* const* d_in, const int* in_sizes, int n_in,
                              void* d_out, int out_size)
{
    const float* x  = (const float*)d_in[0];
    const float* Wi = (const float*)d_in[1];
    const float* bi = (const float*)d_in[2];
    const float* Wk = (const float*)d_in[3];
    const float* bk = (const float*)d_in[4];
    const float* Wq = (const float*)d_in[5];
    const float* bq = (const float*)d_in[6];
    const float* Wv = (const float*)d_in[7];
    const float* bv = (const float*)d_in[8];
    const float* Wo = (const float*)d_in[9];
    const float* bo = (const float*)d_in[10];
    float* out = (float*)d_out;

    float *p_h, *p_kqv, *p_attn, *p_wkqv, *p_bkqv;
    cudaGetSymbolAddress((void**)&p_h,    g_h);
    cudaGetSymbolAddress((void**)&p_kqv,  g_kqv);
    cudaGetSymbolAddress((void**)&p_attn, g_attn);
    cudaGetSymbolAddress((void**)&p_wkqv, g_wkqv);
    cudaGetSymbolAddress((void**)&p_bkqv, g_bkqv);

    cudaFuncSetAttribute(flash_kernel, cudaFuncAttributeMaxDynamicSharedMemorySize, FLASH_SMEM);

    // 1) repack per-head weights into [D, 3D]
    {
        int total = DD * NKQV;
        repack_kernel<<<(total + 255) / 256, 256>>>(Wk, bk, Wq, bq, Wv, bv);
    }
    // 2) h = x @ Wi + bi          [16384,1024]
    {
        dim3 grid(DD / BN, MT / BM);
        sgemm_bias<<<grid, 256>>>(x, Wi, bi, p_h, MT, DD, DD);
    }
    // 3) kqv = h @ Wkqv + bkqv    [16384,3072]
    {
        dim3 grid(NKQV / BN, MT / BM);
        sgemm_bias<<<grid, 256>>>(p_h, p_wkqv, p_bkqv, p_kqv, MT, NKQV, DD);
    }
    // 4) fused causal attention -> g_attn [16384,1024]
    {
        dim3 grid(TT / 64, HH, BB);
        flash_kernel<<<grid, 256, FLASH_SMEM>>>(p_kqv, p_attn);
    }
    // 5) out = attn @ Wo + bo     [16384,1024]
    {
        dim3 grid(DD / BN, MT / BM);
        sgemm_bias<<<grid, 256>>>(p_attn, Wo, bo, out, MT, DD, DD);
    }
}

// round 7
// speedup vs baseline: 2.0582x; 2.0582x over previous
#include <cuda_runtime.h>
#include <cuda_bf16.h>
#include <cstdint>
#include <math.h>

// ---------------- problem constants ----------------
#define BB 32
#define TT 512
#define DD 1024
#define HH 16
#define HD 64
#define MT (BB*TT)          // 16384
#define NKQV (3*DD)         // 3072
#define NALL (5*DD)         // 5120 combined weight rows: [Wi | Wkqv | Wo], layout [N][K]

typedef __nv_bfloat16 bf16;
typedef __nv_bfloat162 bf162;

// ---------------- scratch (device globals; no cudaMalloc allowed) ----------
__device__ __align__(256) bf16 g_xhi[(size_t)MT*DD], g_xlo[(size_t)MT*DD];
__device__ __align__(256) bf16 g_hhi[(size_t)MT*DD], g_hlo[(size_t)MT*DD];
__device__ __align__(256) float g_kqv[(size_t)MT*NKQV];
__device__ __align__(256) bf16 g_ahi[(size_t)MT*DD], g_alo[(size_t)MT*DD];
__device__ __align__(256) bf16 g_whi[(size_t)NALL*DD], g_wlo[(size_t)NALL*DD];
__device__ __align__(256) float g_bias[NALL];

// ---------------- PTX helpers (all sm_80-generic; no 'a' features) ---------
__device__ __forceinline__ uint32_t smem_u32(const void* p) {
    uint32_t a;
    asm("{ .reg .u64 t; cvta.to.shared.u64 t, %1; cvt.u32.u64 %0, t; }" : "=r"(a) : "l"(p));
    return a;
}
__device__ __forceinline__ void cp16(uint32_t dst, const void* src) {
    asm volatile("cp.async.cg.shared.global [%0], [%1], 16;" :: "r"(dst), "l"(src) : "memory");
}
#define CP_COMMIT() asm volatile("cp.async.commit_group;" ::: "memory")
#define CP_WAIT(N)  asm volatile("cp.async.wait_group %0;" :: "n"(N) : "memory")

__device__ __forceinline__ void ldsm4(uint32_t r[4], uint32_t addr) {
    asm volatile("ldmatrix.sync.aligned.m8n8.x4.shared.b16 {%0,%1,%2,%3}, [%4];"
        : "=r"(r[0]), "=r"(r[1]), "=r"(r[2]), "=r"(r[3]) : "r"(addr));
}
__device__ __forceinline__ void mma_bf16(float c[4], const uint32_t a[4],
                                         uint32_t b0, uint32_t b1) {
    asm volatile("mma.sync.aligned.m16n8k16.row.col.f32.bf16.bf16.f32 "
        "{%0,%1,%2,%3}, {%4,%5,%6,%7}, {%8,%9}, {%0,%1,%2,%3};"
        : "+f"(c[0]), "+f"(c[1]), "+f"(c[2]), "+f"(c[3])
        : "r"(a[0]), "r"(a[1]), "r"(a[2]), "r"(a[3]), "r"(b0), "r"(b1));
}

__device__ __forceinline__ void split_bf16(float v, bf16& hi, bf16& lo) {
    hi = __float2bfloat16_rn(v);
    lo = __float2bfloat16_rn(v - __bfloat162float(hi));
}

// ---------------- prep kernels ----------------
__global__ void prep_w(const float* __restrict__ Wi, const float* __restrict__ bi,
                       const float* __restrict__ Wk, const float* __restrict__ bk,
                       const float* __restrict__ Wq, const float* __restrict__ bq,
                       const float* __restrict__ Wv, const float* __restrict__ bv,
                       const float* __restrict__ Wo, const float* __restrict__ bo)
{
    int idx = blockIdx.x * blockDim.x + threadIdx.x;
    if (idx < NALL * DD) {
        int n = idx >> 10;
        int k = idx & 1023;
        float w;
        if (n < DD) {
            w = Wi[(size_t)k * DD + n];
        } else if (n < 4 * DD) {
            int m = n - DD;
            int sec = m >> 10;
            int mm = m & 1023;
            const float* W = (sec == 0) ? Wk : (sec == 1) ? Wq : Wv;
            w = W[(size_t)(mm >> 6) * (DD * HD) + (size_t)k * HD + (mm & 63)];
        } else {
            w = Wo[(size_t)k * DD + (n - 4 * DD)];
        }
        split_bf16(w, g_whi[idx], g_wlo[idx]);
    }
    if (idx < NALL) {
        float b;
        if (idx < DD) b = bi[idx];
        else if (idx < 4 * DD) {
            int m = idx - DD;
            b = ((m >> 10) == 0 ? bk : ((m >> 10) == 1 ? bq : bv))[m & 1023];
        } else b = bo[idx - 4 * DD];
        g_bias[idx] = b;
    }
}

__global__ void prep_x(const float* __restrict__ x)
{
    size_t idx = (size_t)blockIdx.x * blockDim.x + threadIdx.x;
    if (idx < (size_t)MT * DD) {
        split_bf16(x[idx], g_xhi[idx], g_xlo[idx]);
    }
}

// ---------------- mma.sync 3xBF16 GEMM ----------------
// C[M,N] = A[M,K] @ W^T + bias, A split hi/lo [M][K], W split hi/lo [N][K].
// BM=128, BN=128, BK=32. 256 threads = 8 warps (2 m x 4 n), warp tile 64x32.
// smem per buffer: Ahi/Alo/Bhi/Blo each 128 rows x 40 halves (pad) = 10240B -> 40960B; x2.
#define GSTRIDE 40
#define GREG    10240u
#define GBUF    40960u
#define GEMM_SMEM (2 * GBUF)

__global__ __launch_bounds__(256)
void gemm_bf16x3(const bf16* __restrict__ Ahi, const bf16* __restrict__ Alo,
                 const bf16* __restrict__ Bhi, const bf16* __restrict__ Blo,
                 const float* __restrict__ bias,
                 float* __restrict__ C0, bf16* __restrict__ Chi, bf16* __restrict__ Clo,
                 int K, int ldC, int mode)
{
    extern __shared__ char smg[];
    const uint32_t smb = smem_u32(smg);
    const int tid = threadIdx.x;
    const int lane = tid & 31;
    const int wid = tid >> 5;
    const int warp_m = wid >> 2;        // 0..1
    const int warp_n = wid & 3;         // 0..3
    const int bm = blockIdx.y * 128;
    const int bn = blockIdx.x * 128;

    // ---- per-thread load mapping: 2 rows per region (r0 and r0+64), chunk q ----
    const int r0 = tid >> 2;            // 0..63
    const int q0 = tid & 3;             // 16B chunk in row
    const size_t a_src0 = (size_t)(bm + r0) * K + q0 * 8;
    const size_t a_src1 = a_src0 + (size_t)64 * K;
    const size_t b_src0 = (size_t)(bn + r0) * K + q0 * 8;
    const size_t b_src1 = b_src0 + (size_t)64 * K;
    const uint32_t d0 = (uint32_t)(r0 * (GSTRIDE * 2) + q0 * 16);
    const uint32_t d1 = d0 + 64u * (GSTRIDE * 2);

    const int nchunks = K >> 5;         // 32

#define LOAD_TILES(c, buf) do { \
    const uint32_t bb = smb + (uint32_t)(buf) * GBUF; \
    const size_t ko = (size_t)(c) * 32; \
    cp16(bb + 0*GREG + d0, Ahi + a_src0 + ko); \
    cp16(bb + 0*GREG + d1, Ahi + a_src1 + ko); \
    cp16(bb + 1*GREG + d0, Alo + a_src0 + ko); \
    cp16(bb + 1*GREG + d1, Alo + a_src1 + ko); \
    cp16(bb + 2*GREG + d0, Bhi + b_src0 + ko); \
    cp16(bb + 2*GREG + d1, Bhi + b_src1 + ko); \
    cp16(bb + 3*GREG + d0, Blo + b_src0 + ko); \
    cp16(bb + 3*GREG + d1, Blo + b_src1 + ko); \
    CP_COMMIT(); \
} while (0)

    // ---- fragment address components (ldmatrix lane mapping) ----
    const int row_in = lane & 7;
    const int grp = lane >> 3;
    // A: matrices ordered (m0,k0),(m8,k0),(m0,k8),(m8,k8)
    const int a_m = warp_m * 64 + (grp & 1) * 8 + row_in;
    const int a_k = (grp >> 1) * 8;
    // B: matrices ordered (n0,k0),(n0,k8),(n8,k0),(n8,k8)
    const int b_n = warp_n * 32 + (grp >> 1) * 8 + row_in;
    const int b_k = (grp & 1) * 8;

    float c[4][4][4];
#pragma unroll
    for (int mi = 0; mi < 4; mi++)
#pragma unroll
        for (int ni = 0; ni < 4; ni++)
#pragma unroll
            for (int r = 0; r < 4; r++) c[mi][ni][r] = 0.f;

    LOAD_TILES(0, 0);

    for (int cc = 0; cc < nchunks; cc++) {
        if (cc + 1 < nchunks) {
            LOAD_TILES(cc + 1, (cc + 1) & 1);
            CP_WAIT(1);
        } else {
            CP_WAIT(0);
        }
        __syncthreads();

        const uint32_t bb = smb + (uint32_t)(cc & 1) * GBUF;
#pragma unroll
        for (int ks = 0; ks < 2; ks++) {
            const int kofs = ks * 16;
            uint32_t ah[4][4], al[4][4];
#pragma unroll
            for (int mi = 0; mi < 4; mi++) {
                uint32_t off = (uint32_t)(((a_m + mi * 16) * GSTRIDE + a_k + kofs) * 2);
                ldsm4(ah[mi], bb + 0 * GREG + off);
                ldsm4(al[mi], bb + 1 * GREG + off);
            }
            uint32_t bh[2][4], bl[2][4];
#pragma unroll
            for (int n2 = 0; n2 < 2; n2++) {
                uint32_t off = (uint32_t)(((b_n + n2 * 16) * GSTRIDE + b_k + kofs) * 2);
                ldsm4(bh[n2], bb + 2 * GREG + off);
                ldsm4(bl[n2], bb + 3 * GREG + off);
            }
            // bh[n2] = {b0(ni=2*n2), b1(ni), b0(ni+1), b1(ni+1)}
#pragma unroll
            for (int mi = 0; mi < 4; mi++) {
#pragma unroll
                for (int ni = 0; ni < 4; ni++) {
                    const int n2 = ni >> 1, hb = (ni & 1) * 2;
                    mma_bf16(c[mi][ni], ah[mi], bh[n2][hb], bh[n2][hb + 1]);   // hi*hi
                    mma_bf16(c[mi][ni], ah[mi], bl[n2][hb], bl[n2][hb + 1]);   // hi*lo
                    mma_bf16(c[mi][ni], al[mi], bh[n2][hb], bh[n2][hb + 1]);   // lo*hi
                }
            }
        }
        __syncthreads();
    }

    // ---- epilogue: C fragment (g=lane>>2, t=lane&3): c0=C[g][2t] c1=C[g][2t+1] c2=C[g+8][2t] c3=C[g+8][2t+1]
    const int g = lane >> 2;
    const int t = lane & 3;
#pragma unroll
    for (int mi = 0; mi < 4; mi++) {
#pragma unroll
        for (int ni = 0; ni < 4; ni++) {
            const int col = bn + warp_n * 32 + ni * 8 + 2 * t;
            const float bx = bias[col], by = bias[col + 1];
            const int row0 = bm + warp_m * 64 + mi * 16 + g;
            const int row1 = row0 + 8;
            float v00 = c[mi][ni][0] + bx, v01 = c[mi][ni][1] + by;
            float v10 = c[mi][ni][2] + bx, v11 = c[mi][ni][3] + by;
            if (mode == 0) {
                *(float2*)(C0 + (size_t)row0 * ldC + col) = make_float2(v00, v01);
                *(float2*)(C0 + (size_t)row1 * ldC + col) = make_float2(v10, v11);
            } else {
                bf16 h0, l0, h1, l1;
                split_bf16(v00, h0, l0); split_bf16(v01, h1, l1);
                *(bf162*)(Chi + (size_t)row0 * ldC + col) = bf162(h0, h1);
                *(bf162*)(Clo + (size_t)row0 * ldC + col) = bf162(l0, l1);
                split_bf16(v10, h0, l0); split_bf16(v11, h1, l1);
                *(bf162*)(Chi + (size_t)row1 * ldC + col) = bf162(h0, h1);
                *(bf162*)(Clo + (size_t)row1 * ldC + col) = bf162(l0, l1);
            }
        }
    }
#undef LOAD_TILES
}

// ---------------- fused causal flash attention (fp32) ----------------
// Reference: wei[t,s] = k_t . q_s, causal mask, softmax over s, out = wei@v.
// Epilogue writes bf16 hi/lo split for the final GEMM.
#define FLASH_SMEM ((3 * 64 * 65 + 64 * 64) * (int)sizeof(float))

__global__ __launch_bounds__(256)
void flash_kernel(const float* __restrict__ kqv,
                  bf16* __restrict__ outhi, bf16* __restrict__ outlo)
{
    extern __shared__ float smf[];
    float* Qs = smf;
    float* Ks = Qs + 64 * 65;
    float* Ps = Ks + 64 * 65;
    float* Vs = Ps + 64 * 65;

    const int tid = threadIdx.x;
    const int tx = tid & 15;
    const int ty = tid >> 4;
    const int tt = blockIdx.x;
    const int h  = blockIdx.y;
    const int b  = blockIdx.z;

    const size_t base = (size_t)b * TT * NKQV + (size_t)h * HD;

#pragma unroll
    for (int rep = 0; rep < 4; rep++) {
        int i = (tid >> 4) + rep * 16;
        int e = (tid & 15) * 4;
        float4 v = *(const float4*)(kqv + base + (size_t)(tt * 64 + i) * NKQV + e);
        Qs[(e + 0) * 65 + i] = v.x;
        Qs[(e + 1) * 65 + i] = v.y;
        Qs[(e + 2) * 65 + i] = v.z;
        Qs[(e + 3) * 65 + i] = v.w;
    }

    float m_i[4], l_i[4], o[4][4];
#pragma unroll
    for (int i = 0; i < 4; i++) {
        m_i[i] = -1e30f; l_i[i] = 0.f;
#pragma unroll
        for (int e = 0; e < 4; e++) o[i][e] = 0.f;
    }

    for (int st = 0; st <= tt; st++) {
        __syncthreads();
#pragma unroll
        for (int rep = 0; rep < 4; rep++) {
            int j = (tid >> 4) + rep * 16;
            int e = (tid & 15) * 4;
            float4 vk = *(const float4*)(kqv + base + 1024 + (size_t)(st * 64 + j) * NKQV + e);
            Ks[(e + 0) * 65 + j] = vk.x;
            Ks[(e + 1) * 65 + j] = vk.y;
            Ks[(e + 2) * 65 + j] = vk.z;
            Ks[(e + 3) * 65 + j] = vk.w;
            float4 vv = *(const float4*)(kqv + base + 2048 + (size_t)(st * 64 + j) * NKQV + e);
            *(float4*)&Vs[j * 64 + e] = vv;
        }
        __syncthreads();

        float s_acc[4][4];
#pragma unroll
        for (int i = 0; i < 4; i++)
#pragma unroll
            for (int j = 0; j < 4; j++) s_acc[i][j] = 0.f;

#pragma unroll 8
        for (int e = 0; e < 64; e++) {
            float a[4], bq[4];
#pragma unroll
            for (int i = 0; i < 4; i++) a[i] = Qs[e * 65 + ty * 4 + i];
#pragma unroll
            for (int j = 0; j < 4; j++) bq[j] = Ks[e * 65 + tx * 4 + j];
#pragma unroll
            for (int i = 0; i < 4; i++)
#pragma unroll
                for (int j = 0; j < 4; j++) s_acc[i][j] = fmaf(a[i], bq[j], s_acc[i][j]);
        }

        if (st == tt) {
#pragma unroll
            for (int i = 0; i < 4; i++)
#pragma unroll
                for (int j = 0; j < 4; j++)
                    if (tx * 4 + j > ty * 4 + i) s_acc[i][j] = -1e30f;
        }

#pragma unroll
        for (int i = 0; i < 4; i++) {
            float mx = fmaxf(fmaxf(s_acc[i][0], s_acc[i][1]), fmaxf(s_acc[i][2], s_acc[i][3]));
#pragma unroll
            for (int off = 1; off < 16; off <<= 1)
                mx = fmaxf(mx, __shfl_xor_sync(0xffffffffu, mx, off, 16));
            float m_new = fmaxf(m_i[i], mx);
            float scale = __expf(m_i[i] - m_new);
            float lsum = 0.f;
#pragma unroll
            for (int j = 0; j < 4; j++) {
                float p = __expf(s_acc[i][j] - m_new);
                s_acc[i][j] = p;
                lsum += p;
            }
#pragma unroll
            for (int off = 1; off < 16; off <<= 1)
                lsum += __shfl_xor_sync(0xffffffffu, lsum, off, 16);
            l_i[i] = l_i[i] * scale + lsum;
            m_i[i] = m_new;
#pragma unroll
            for (int e = 0; e < 4; e++) o[i][e] *= scale;
        }

#pragma unroll
        for (int i = 0; i < 4; i++)
#pragma unroll
            for (int j = 0; j < 4; j++)
                Ps[(tx * 4 + j) * 65 + ty * 4 + i] = s_acc[i][j];
        __syncthreads();

#pragma unroll 8
        for (int s = 0; s < 64; s++) {
            float a[4], bv[4];
#pragma unroll
            for (int i = 0; i < 4; i++) a[i] = Ps[s * 65 + ty * 4 + i];
#pragma unroll
            for (int e = 0; e < 4; e++) bv[e] = Vs[s * 64 + tx * 4 + e];
#pragma unroll
            for (int i = 0; i < 4; i++)
#pragma unroll
                for (int e = 0; e < 4; e++) o[i][e] = fmaf(a[i], bv[e], o[i][e]);
        }
    }

#pragma unroll
    for (int i = 0; i < 4; i++) {
        float inv = 1.f / l_i[i];
        int t_g = tt * 64 + ty * 4 + i;
        size_t ofs = (size_t)(b * TT + t_g) * DD + h * HD + tx * 4;
        float v0 = o[i][0] * inv, v1 = o[i][1] * inv, v2 = o[i][2] * inv, v3 = o[i][3] * inv;
        bf16 h0, l0, h1, l1, h2, l2, h3, l3;
        split_bf16(v0, h0, l0); split_bf16(v1, h1, l1);
        split_bf16(v2, h2, l2); split_bf16(v3, h3, l3);
        *(bf162*)(outhi + ofs)     = bf162(h0, h1);
        *(bf162*)(outhi + ofs + 2) = bf162(h2, h3);
        *(bf162*)(outlo + ofs)     = bf162(l0, l1);
        *(bf162*)(outlo + ofs + 2) = bf162(l2, l3);
    }
}

// ---------------- launch ----------------
extern "C" void kernel_launch(void* const* d_in, const int* in_sizes, int n_in,
                              void* d_out, int out_size)
{
    const float* x  = (const float*)d_in[0];
    const float* Wi = (const float*)d_in[1];
    const float* bi = (const float*)d_in[2];
    const float* Wk = (const float*)d_in[3];
    const float* bk = (const float*)d_in[4];
    const float* Wq = (const float*)d_in[5];
    const float* bq = (const float*)d_in[6];
    const float* Wv = (const float*)d_in[7];
    const float* bv = (const float*)d_in[8];
    const float* Wo = (const float*)d_in[9];
    const float* bo = (const float*)d_in[10];
    float* out = (float*)d_out;

    bf16 *p_xhi, *p_xlo, *p_hhi, *p_hlo, *p_ahi, *p_alo, *p_whi, *p_wlo;
    float *p_kqv, *p_bias;
    cudaGetSymbolAddress((void**)&p_xhi, g_xhi);
    cudaGetSymbolAddress((void**)&p_xlo, g_xlo);
    cudaGetSymbolAddress((void**)&p_hhi, g_hhi);
    cudaGetSymbolAddress((void**)&p_hlo, g_hlo);
    cudaGetSymbolAddress((void**)&p_kqv, g_kqv);
    cudaGetSymbolAddress((void**)&p_ahi, g_ahi);
    cudaGetSymbolAddress((void**)&p_alo, g_alo);
    cudaGetSymbolAddress((void**)&p_whi, g_whi);
    cudaGetSymbolAddress((void**)&p_wlo, g_wlo);
    cudaGetSymbolAddress((void**)&p_bias, g_bias);

    cudaFuncSetAttribute(gemm_bf16x3, cudaFuncAttributeMaxDynamicSharedMemorySize, GEMM_SMEM);
    cudaFuncSetAttribute(flash_kernel, cudaFuncAttributeMaxDynamicSharedMemorySize, FLASH_SMEM);

    // prep: weights (repack+transpose+split) and x (split)
    prep_w<<<(NALL * DD + 255) / 256, 256>>>(Wi, bi, Wk, bk, Wq, bq, Wv, bv, Wo, bo);
    prep_x<<<(int)(((size_t)MT * DD + 255) / 256), 256>>>(x);

    // h = x @ Wi + bi  -> bf16 hi/lo (mode 1)
    {
        dim3 grid(DD / 128, MT / 128);
        gemm_bf16x3<<<grid, 256, GEMM_SMEM>>>(p_xhi, p_xlo, p_whi, p_wlo, p_bias,
                                              nullptr, p_hhi, p_hlo, DD, DD, 1);
    }
    // kqv = h @ Wkqv + bkqv -> fp32 (mode 0)
    {
        dim3 grid(NKQV / 128, MT / 128);
        gemm_bf16x3<<<grid, 256, GEMM_SMEM>>>(p_hhi, p_hlo,
            p_whi + (size_t)DD * DD, p_wlo + (size_t)DD * DD, p_bias + DD,
            p_kqv, nullptr, nullptr, DD, NKQV, 0);
    }
    // fused causal attention -> attn bf16 hi/lo
    {
        dim3 grid(TT / 64, HH, BB);
        flash_kernel<<<grid, 256, FLASH_SMEM>>>(p_kqv, p_ahi, p_alo);
    }
    // out = attn @ Wo + bo -> fp32 to d_out
    {
        dim3 grid(DD / 128, MT / 128);
        gemm_bf16x3<<<grid, 256, GEMM_SMEM>>>(p_ahi, p_alo,
            p_whi + (size_t)(4 * DD) * DD, p_wlo + (size_t)(4 * DD) * DD, p_bias + 4 * DD,
            out, nullptr, nullptr, DD, DD, 0);
    }
}

// round 8
// speedup vs baseline: 2.4042x; 1.1681x over previous
#include <cuda_runtime.h>
#include <cuda_bf16.h>
#include <cstdint>
#include <math.h>

// ---------------- problem constants ----------------
#define BB 32
#define TT 512
#define DD 1024
#define HH 16
#define HD 64
#define MT (BB*TT)          // 16384
#define NKQV (3*DD)         // 3072
#define NALL (5*DD)         // 5120 combined weight rows: [Wi | Wkqv | Wo], layout [N][K]

typedef __nv_bfloat16 bf16;
typedef __nv_bfloat162 bf162;

// ---------------- scratch (device globals; no cudaMalloc allowed) ----------
__device__ __align__(256) bf16 g_xhi[(size_t)MT*DD], g_xlo[(size_t)MT*DD];
__device__ __align__(256) bf16 g_hhi[(size_t)MT*DD], g_hlo[(size_t)MT*DD];
__device__ __align__(256) bf16 g_kqvhi[(size_t)MT*NKQV], g_kqvlo[(size_t)MT*NKQV];
__device__ __align__(256) bf16 g_ahi[(size_t)MT*DD], g_alo[(size_t)MT*DD];
__device__ __align__(256) bf16 g_whi[(size_t)NALL*DD], g_wlo[(size_t)NALL*DD];
__device__ __align__(256) float g_bias[NALL];

// ---------------- PTX helpers (all sm_80-generic; no 'a' features) ---------
__device__ __forceinline__ uint32_t smem_u32(const void* p) {
    uint32_t a;
    asm("{ .reg .u64 t; cvta.to.shared.u64 t, %1; cvt.u32.u64 %0, t; }" : "=r"(a) : "l"(p));
    return a;
}
__device__ __forceinline__ void cp16(uint32_t dst, const void* src) {
    asm volatile("cp.async.cg.shared.global [%0], [%1], 16;" :: "r"(dst), "l"(src) : "memory");
}
#define CP_COMMIT() asm volatile("cp.async.commit_group;" ::: "memory")
#define CP_WAIT(N)  asm volatile("cp.async.wait_group %0;" :: "n"(N) : "memory")

__device__ __forceinline__ void ldsm4(uint32_t r[4], uint32_t addr) {
    asm volatile("ldmatrix.sync.aligned.m8n8.x4.shared.b16 {%0,%1,%2,%3}, [%4];"
        : "=r"(r[0]), "=r"(r[1]), "=r"(r[2]), "=r"(r[3]) : "r"(addr));
}
__device__ __forceinline__ void ldsm4t(uint32_t r[4], uint32_t addr) {
    asm volatile("ldmatrix.sync.aligned.m8n8.x4.trans.shared.b16 {%0,%1,%2,%3}, [%4];"
        : "=r"(r[0]), "=r"(r[1]), "=r"(r[2]), "=r"(r[3]) : "r"(addr));
}
__device__ __forceinline__ void mma_bf16(float c[4], const uint32_t a[4],
                                         uint32_t b0, uint32_t b1) {
    asm volatile("mma.sync.aligned.m16n8k16.row.col.f32.bf16.bf16.f32 "
        "{%0,%1,%2,%3}, {%4,%5,%6,%7}, {%8,%9}, {%0,%1,%2,%3};"
        : "+f"(c[0]), "+f"(c[1]), "+f"(c[2]), "+f"(c[3])
        : "r"(a[0]), "r"(a[1]), "r"(a[2]), "r"(a[3]), "r"(b0), "r"(b1));
}

__device__ __forceinline__ void split_bf16(float v, bf16& hi, bf16& lo) {
    hi = __float2bfloat16_rn(v);
    lo = __float2bfloat16_rn(v - __bfloat162float(hi));
}
// pack two floats as bf16x2 (e0 = low half) returning hi-pair; lo-pair via out param
__device__ __forceinline__ uint32_t pack_split(float e0, float e1, uint32_t& lopair) {
    bf16 h0, l0, h1, l1;
    split_bf16(e0, h0, l0);
    split_bf16(e1, h1, l1);
    uint32_t hp, lp;
    asm("mov.b32 %0, {%1,%2};" : "=r"(hp) : "h"(*(unsigned short*)&h0), "h"(*(unsigned short*)&h1));
    asm("mov.b32 %0, {%1,%2};" : "=r"(lp) : "h"(*(unsigned short*)&l0), "h"(*(unsigned short*)&l1));
    lopair = lp;
    return hp;
}

// ---------------- prep kernels ----------------
__global__ void prep_w(const float* __restrict__ Wi, const float* __restrict__ bi,
                       const float* __restrict__ Wk, const float* __restrict__ bk,
                       const float* __restrict__ Wq, const float* __restrict__ bq,
                       const float* __restrict__ Wv, const float* __restrict__ bv,
                       const float* __restrict__ Wo, const float* __restrict__ bo)
{
    int idx = blockIdx.x * blockDim.x + threadIdx.x;
    if (idx < NALL * DD) {
        int n = idx >> 10;
        int k = idx & 1023;
        float w;
        if (n < DD) {
            w = Wi[(size_t)k * DD + n];
        } else if (n < 4 * DD) {
            int m = n - DD;
            int sec = m >> 10;
            int mm = m & 1023;
            const float* W = (sec == 0) ? Wk : (sec == 1) ? Wq : Wv;
            w = W[(size_t)(mm >> 6) * (DD * HD) + (size_t)k * HD + (mm & 63)];
        } else {
            w = Wo[(size_t)k * DD + (n - 4 * DD)];
        }
        split_bf16(w, g_whi[idx], g_wlo[idx]);
    }
    if (idx < NALL) {
        float b;
        if (idx < DD) b = bi[idx];
        else if (idx < 4 * DD) {
            int m = idx - DD;
            b = ((m >> 10) == 0 ? bk : ((m >> 10) == 1 ? bq : bv))[m & 1023];
        } else b = bo[idx - 4 * DD];
        g_bias[idx] = b;
    }
}

__global__ void prep_x(const float* __restrict__ x)
{
    size_t idx = (size_t)blockIdx.x * blockDim.x + threadIdx.x;
    if (idx < (size_t)MT * DD) {
        split_bf16(x[idx], g_xhi[idx], g_xlo[idx]);
    }
}

// ---------------- mma.sync 3xBF16 GEMM ----------------
// C[M,N] = A[M,K] @ W^T + bias, A split hi/lo [M][K], W split hi/lo [N][K].
// BM=128, BN=128, BK=32. 256 threads = 8 warps (2 m x 4 n), warp tile 64x32.
#define GSTRIDE 40
#define GREG    10240u
#define GBUF    40960u
#define GEMM_SMEM (2 * GBUF)

__global__ __launch_bounds__(256)
void gemm_bf16x3(const bf16* __restrict__ Ahi, const bf16* __restrict__ Alo,
                 const bf16* __restrict__ Bhi, const bf16* __restrict__ Blo,
                 const float* __restrict__ bias,
                 float* __restrict__ C0, bf16* __restrict__ Chi, bf16* __restrict__ Clo,
                 int K, int ldC, int mode)
{
    extern __shared__ char smg[];
    const uint32_t smb = smem_u32(smg);
    const int tid = threadIdx.x;
    const int lane = tid & 31;
    const int wid = tid >> 5;
    const int warp_m = wid >> 2;
    const int warp_n = wid & 3;
    const int bm = blockIdx.y * 128;
    const int bn = blockIdx.x * 128;

    const int r0 = tid >> 2;
    const int q0 = tid & 3;
    const size_t a_src0 = (size_t)(bm + r0) * K + q0 * 8;
    const size_t a_src1 = a_src0 + (size_t)64 * K;
    const size_t b_src0 = (size_t)(bn + r0) * K + q0 * 8;
    const size_t b_src1 = b_src0 + (size_t)64 * K;
    const uint32_t d0 = (uint32_t)(r0 * (GSTRIDE * 2) + q0 * 16);
    const uint32_t d1 = d0 + 64u * (GSTRIDE * 2);

    const int nchunks = K >> 5;

#define LOAD_TILES(c, buf) do { \
    const uint32_t bb = smb + (uint32_t)(buf) * GBUF; \
    const size_t ko = (size_t)(c) * 32; \
    cp16(bb + 0*GREG + d0, Ahi + a_src0 + ko); \
    cp16(bb + 0*GREG + d1, Ahi + a_src1 + ko); \
    cp16(bb + 1*GREG + d0, Alo + a_src0 + ko); \
    cp16(bb + 1*GREG + d1, Alo + a_src1 + ko); \
    cp16(bb + 2*GREG + d0, Bhi + b_src0 + ko); \
    cp16(bb + 2*GREG + d1, Bhi + b_src1 + ko); \
    cp16(bb + 3*GREG + d0, Blo + b_src0 + ko); \
    cp16(bb + 3*GREG + d1, Blo + b_src1 + ko); \
    CP_COMMIT(); \
} while (0)

    const int row_in = lane & 7;
    const int grp = lane >> 3;
    const int a_m = warp_m * 64 + (grp & 1) * 8 + row_in;
    const int a_k = (grp >> 1) * 8;
    const int b_n = warp_n * 32 + (grp >> 1) * 8 + row_in;
    const int b_k = (grp & 1) * 8;

    float c[4][4][4];
#pragma unroll
    for (int mi = 0; mi < 4; mi++)
#pragma unroll
        for (int ni = 0; ni < 4; ni++)
#pragma unroll
            for (int r = 0; r < 4; r++) c[mi][ni][r] = 0.f;

    LOAD_TILES(0, 0);

    for (int cc = 0; cc < nchunks; cc++) {
        if (cc + 1 < nchunks) {
            LOAD_TILES(cc + 1, (cc + 1) & 1);
            CP_WAIT(1);
        } else {
            CP_WAIT(0);
        }
        __syncthreads();

        const uint32_t bb = smb + (uint32_t)(cc & 1) * GBUF;
#pragma unroll
        for (int ks = 0; ks < 2; ks++) {
            const int kofs = ks * 16;
            uint32_t ah[4][4], al[4][4];
#pragma unroll
            for (int mi = 0; mi < 4; mi++) {
                uint32_t off = (uint32_t)(((a_m + mi * 16) * GSTRIDE + a_k + kofs) * 2);
                ldsm4(ah[mi], bb + 0 * GREG + off);
                ldsm4(al[mi], bb + 1 * GREG + off);
            }
            uint32_t bh[2][4], bl[2][4];
#pragma unroll
            for (int n2 = 0; n2 < 2; n2++) {
                uint32_t off = (uint32_t)(((b_n + n2 * 16) * GSTRIDE + b_k + kofs) * 2);
                ldsm4(bh[n2], bb + 2 * GREG + off);
                ldsm4(bl[n2], bb + 3 * GREG + off);
            }
#pragma unroll
            for (int mi = 0; mi < 4; mi++) {
#pragma unroll
                for (int ni = 0; ni < 4; ni++) {
                    const int n2 = ni >> 1, hb = (ni & 1) * 2;
                    mma_bf16(c[mi][ni], ah[mi], bh[n2][hb], bh[n2][hb + 1]);
                    mma_bf16(c[mi][ni], ah[mi], bl[n2][hb], bl[n2][hb + 1]);
                    mma_bf16(c[mi][ni], al[mi], bh[n2][hb], bh[n2][hb + 1]);
                }
            }
        }
        __syncthreads();
    }

    const int g = lane >> 2;
    const int t = lane & 3;
#pragma unroll
    for (int mi = 0; mi < 4; mi++) {
#pragma unroll
        for (int ni = 0; ni < 4; ni++) {
            const int col = bn + warp_n * 32 + ni * 8 + 2 * t;
            const float bx = bias[col], by = bias[col + 1];
            const int row0 = bm + warp_m * 64 + mi * 16 + g;
            const int row1 = row0 + 8;
            float v00 = c[mi][ni][0] + bx, v01 = c[mi][ni][1] + by;
            float v10 = c[mi][ni][2] + bx, v11 = c[mi][ni][3] + by;
            if (mode == 0) {
                *(float2*)(C0 + (size_t)row0 * ldC + col) = make_float2(v00, v01);
                *(float2*)(C0 + (size_t)row1 * ldC + col) = make_float2(v10, v11);
            } else {
                bf16 h0, l0, h1, l1;
                split_bf16(v00, h0, l0); split_bf16(v01, h1, l1);
                *(bf162*)(Chi + (size_t)row0 * ldC + col) = bf162(h0, h1);
                *(bf162*)(Clo + (size_t)row0 * ldC + col) = bf162(l0, l1);
                split_bf16(v10, h0, l0); split_bf16(v11, h1, l1);
                *(bf162*)(Chi + (size_t)row1 * ldC + col) = bf162(h0, h1);
                *(bf162*)(Clo + (size_t)row1 * ldC + col) = bf162(l0, l1);
            }
        }
    }
#undef LOAD_TILES
}

// ---------------- tensor-core causal flash attention (3xBF16) -------------
// Reference: wei[t,s] = k_t . q_s, causal mask, softmax over s, out = wei@v.
// Q := k-section (col 0), K := q-section (+1024), V := v-section (+2048).
// CTA = (tt, h, b), 4 warps x 16 rows = 64-row tile, 64-col K/V tiles.
// smem halves stride 72 (144B rows -> conflict-free ldmatrix).
#define QSTR 72
#define FA_ARR 9216u
#define FA_BUF0 18432u
#define FA_BUFSZ 36864u
#define FLASH_SMEM 92160

__global__ __launch_bounds__(128)
void flash_mma(const bf16* __restrict__ khi, const bf16* __restrict__ klo,
               bf16* __restrict__ outhi, bf16* __restrict__ outlo)
{
    extern __shared__ char smf[];
    const uint32_t smb = smem_u32(smf);
    const int tid = threadIdx.x;
    const int lane = tid & 31;
    const int warp = tid >> 5;
    const int grp = lane >> 3, row_in = lane & 7;
    const int g = lane >> 2, t = lane & 3;
    const int tt = blockIdx.x, h = blockIdx.y, b = blockIdx.z;

    const size_t bh = (size_t)(b * TT) * NKQV + h * HD;
    const int ldrow = tid >> 1;
    const int ldhc = (tid & 1) * 32;

    // ---- Q tile (hi,lo) cp.async ----
    {
        const bf16* s0 = khi + bh + (size_t)(tt * 64 + ldrow) * NKQV + ldhc;
        const bf16* s1 = klo + bh + (size_t)(tt * 64 + ldrow) * NKQV + ldhc;
        uint32_t d = smb + (uint32_t)(ldrow * QSTR + ldhc) * 2;
        cp16(d, s0); cp16(d + 16, s0 + 8); cp16(d + 32, s0 + 16); cp16(d + 48, s0 + 24);
        d += FA_ARR;
        cp16(d, s1); cp16(d + 16, s1 + 8); cp16(d + 32, s1 + 16); cp16(d + 48, s1 + 24);
    }

#define FA_LOAD_KV(st, buf) do { \
    size_t gofs = bh + (size_t)((st) * 64 + ldrow) * NKQV + ldhc; \
    uint32_t base = smb + FA_BUF0 + (uint32_t)(buf) * FA_BUFSZ + (uint32_t)(ldrow * QSTR + ldhc) * 2; \
    const bf16* p0 = khi + gofs + 1024; \
    cp16(base + 0 * FA_ARR, p0); cp16(base + 0 * FA_ARR + 16, p0 + 8); \
    cp16(base + 0 * FA_ARR + 32, p0 + 16); cp16(base + 0 * FA_ARR + 48, p0 + 24); \
    const bf16* p1 = klo + gofs + 1024; \
    cp16(base + 1 * FA_ARR, p1); cp16(base + 1 * FA_ARR + 16, p1 + 8); \
    cp16(base + 1 * FA_ARR + 32, p1 + 16); cp16(base + 1 * FA_ARR + 48, p1 + 24); \
    const bf16* p2 = khi + gofs + 2048; \
    cp16(base + 2 * FA_ARR, p2); cp16(base + 2 * FA_ARR + 16, p2 + 8); \
    cp16(base + 2 * FA_ARR + 32, p2 + 16); cp16(base + 2 * FA_ARR + 48, p2 + 24); \
    const bf16* p3 = klo + gofs + 2048; \
    cp16(base + 3 * FA_ARR, p3); cp16(base + 3 * FA_ARR + 16, p3 + 8); \
    cp16(base + 3 * FA_ARR + 32, p3 + 16); cp16(base + 3 * FA_ARR + 48, p3 + 24); \
} while (0)

    FA_LOAD_KV(0, 0);
    CP_COMMIT();    // group: Q + KV(0)

    // persistent state
    float m_r[2] = { -1e30f, -1e30f };
    float l_r[2] = { 0.f, 0.f };
    float o[8][4];
#pragma unroll
    for (int ei = 0; ei < 8; ei++)
#pragma unroll
        for (int r = 0; r < 4; r++) o[ei][r] = 0.f;

    uint32_t qh[4][4], ql[4][4];   // Q A-frags, loaded once

    // fragment address components
    const int a_m = warp * 16 + (grp & 1) * 8 + row_in;      // A rows (t)
    const int a_k = (grp >> 1) * 8;                           // A k (e)
    const int b_n = (grp >> 1) * 8 + row_in;                  // B rows (s) for K
    const int b_k = (grp & 1) * 8;                            // B k (e) for K
    const int v_s = (grp & 1) * 8 + row_in;                   // V source row (s)
    const int v_e = (grp >> 1) * 8;                           // V source col (e)

    for (int st = 0; st <= tt; st++) {
        if (st < tt) {
            FA_LOAD_KV(st + 1, (st + 1) & 1);
            CP_COMMIT();
            CP_WAIT(1);
        } else {
            CP_WAIT(0);
        }
        __syncthreads();

        if (st == 0) {
#pragma unroll
            for (int kc = 0; kc < 4; kc++) {
                uint32_t off = (uint32_t)((a_m * QSTR + a_k + kc * 16) * 2);
                ldsm4(qh[kc], smb + off);
                ldsm4(ql[kc], smb + FA_ARR + off);
            }
        }

        const uint32_t kb = smb + FA_BUF0 + (uint32_t)(st & 1) * FA_BUFSZ;

        // ---- S = Q @ K^T (3x split) ----
        float sc[8][4];
#pragma unroll
        for (int ni = 0; ni < 8; ni++)
#pragma unroll
            for (int r = 0; r < 4; r++) sc[ni][r] = 0.f;

#pragma unroll
        for (int kc = 0; kc < 4; kc++) {
            uint32_t kh[4][4], kl[4][4];
#pragma unroll
            for (int j = 0; j < 4; j++) {
                uint32_t off = (uint32_t)(((b_n + j * 16) * QSTR + b_k + kc * 16) * 2);
                ldsm4(kh[j], kb + 0 * FA_ARR + off);
                ldsm4(kl[j], kb + 1 * FA_ARR + off);
            }
#pragma unroll
            for (int j = 0; j < 4; j++) {
                mma_bf16(sc[2 * j],     qh[kc], kh[j][0], kh[j][1]);
                mma_bf16(sc[2 * j],     qh[kc], kl[j][0], kl[j][1]);
                mma_bf16(sc[2 * j],     ql[kc], kh[j][0], kh[j][1]);
                mma_bf16(sc[2 * j + 1], qh[kc], kh[j][2], kh[j][3]);
                mma_bf16(sc[2 * j + 1], qh[kc], kl[j][2], kl[j][3]);
                mma_bf16(sc[2 * j + 1], ql[kc], kh[j][2], kh[j][3]);
            }
        }

        // ---- causal mask on diagonal tile ----
        if (st == tt) {
#pragma unroll
            for (int ni = 0; ni < 8; ni++) {
                int c0 = ni * 8 + 2 * t, c1 = c0 + 1;
                int r0 = warp * 16 + g, r1 = r0 + 8;
                if (c0 > r0) sc[ni][0] = -1e30f;
                if (c1 > r0) sc[ni][1] = -1e30f;
                if (c0 > r1) sc[ni][2] = -1e30f;
                if (c1 > r1) sc[ni][3] = -1e30f;
            }
        }

        // ---- online softmax (rows g and g+8; each row spans 4 lanes) ----
        float mloc0 = -1e30f, mloc1 = -1e30f;
#pragma unroll
        for (int ni = 0; ni < 8; ni++) {
            mloc0 = fmaxf(mloc0, fmaxf(sc[ni][0], sc[ni][1]));
            mloc1 = fmaxf(mloc1, fmaxf(sc[ni][2], sc[ni][3]));
        }
#pragma unroll
        for (int off = 1; off < 4; off <<= 1) {
            mloc0 = fmaxf(mloc0, __shfl_xor_sync(0xffffffffu, mloc0, off));
            mloc1 = fmaxf(mloc1, __shfl_xor_sync(0xffffffffu, mloc1, off));
        }
        float mnew0 = fmaxf(m_r[0], mloc0);
        float mnew1 = fmaxf(m_r[1], mloc1);
        float scale0 = __expf(m_r[0] - mnew0);
        float scale1 = __expf(m_r[1] - mnew1);
        m_r[0] = mnew0; m_r[1] = mnew1;

        float ls0 = 0.f, ls1 = 0.f;
#pragma unroll
        for (int ni = 0; ni < 8; ni++) {
            sc[ni][0] = __expf(sc[ni][0] - mnew0);
            sc[ni][1] = __expf(sc[ni][1] - mnew0);
            sc[ni][2] = __expf(sc[ni][2] - mnew1);
            sc[ni][3] = __expf(sc[ni][3] - mnew1);
            ls0 += sc[ni][0] + sc[ni][1];
            ls1 += sc[ni][2] + sc[ni][3];
        }
#pragma unroll
        for (int off = 1; off < 4; off <<= 1) {
            ls0 += __shfl_xor_sync(0xffffffffu, ls0, off);
            ls1 += __shfl_xor_sync(0xffffffffu, ls1, off);
        }
        l_r[0] = l_r[0] * scale0 + ls0;
        l_r[1] = l_r[1] * scale1 + ls1;

#pragma unroll
        for (int ei = 0; ei < 8; ei++) {
            o[ei][0] *= scale0; o[ei][1] *= scale0;
            o[ei][2] *= scale1; o[ei][3] *= scale1;
        }

        // ---- O += P @ V : P frags from sc registers, V via ldmatrix.trans ----
#pragma unroll
        for (int kc = 0; kc < 4; kc++) {
            uint32_t pa_h[4], pa_l[4];
            pa_h[0] = pack_split(sc[2 * kc][0],     sc[2 * kc][1],     pa_l[0]);
            pa_h[1] = pack_split(sc[2 * kc][2],     sc[2 * kc][3],     pa_l[1]);
            pa_h[2] = pack_split(sc[2 * kc + 1][0], sc[2 * kc + 1][1], pa_l[2]);
            pa_h[3] = pack_split(sc[2 * kc + 1][2], sc[2 * kc + 1][3], pa_l[3]);

            uint32_t vh[4][4], vl[4][4];
#pragma unroll
            for (int j = 0; j < 4; j++) {
                uint32_t off = (uint32_t)(((kc * 16 + v_s) * QSTR + j * 16 + v_e) * 2);
                ldsm4t(vh[j], kb + 2 * FA_ARR + off);
                ldsm4t(vl[j], kb + 3 * FA_ARR + off);
            }
#pragma unroll
            for (int j = 0; j < 4; j++) {
                mma_bf16(o[2 * j],     pa_h, vh[j][0], vh[j][1]);
                mma_bf16(o[2 * j],     pa_h, vl[j][0], vl[j][1]);
                mma_bf16(o[2 * j],     pa_l, vh[j][0], vh[j][1]);
                mma_bf16(o[2 * j + 1], pa_h, vh[j][2], vh[j][3]);
                mma_bf16(o[2 * j + 1], pa_h, vl[j][2], vl[j][3]);
                mma_bf16(o[2 * j + 1], pa_l, vh[j][2], vh[j][3]);
            }
        }
        __syncthreads();   // all warps done reading this buffer
    }

    // ---- epilogue: normalize, split to bf16 hi/lo, write [b*T+t][h*64+e] ----
    const float inv0 = 1.f / l_r[0];
    const float inv1 = 1.f / l_r[1];
    const size_t r0 = (size_t)(b * TT + tt * 64 + warp * 16 + g);
    const size_t r1 = r0 + 8;
#pragma unroll
    for (int ei = 0; ei < 8; ei++) {
        const int col = h * HD + ei * 8 + 2 * t;
        bf16 h0, l0, h1, l1;
        split_bf16(o[ei][0] * inv0, h0, l0);
        split_bf16(o[ei][1] * inv0, h1, l1);
        *(bf162*)(outhi + r0 * DD + col) = bf162(h0, h1);
        *(bf162*)(outlo + r0 * DD + col) = bf162(l0, l1);
        split_bf16(o[ei][2] * inv1, h0, l0);
        split_bf16(o[ei][3] * inv1, h1, l1);
        *(bf162*)(outhi + r1 * DD + col) = bf162(h0, h1);
        *(bf162*)(outlo + r1 * DD + col) = bf162(l0, l1);
    }
#undef FA_LOAD_KV
}

// ---------------- launch ----------------
extern "C" void kernel_launch(void* const* d_in, const int* in_sizes, int n_in,
                              void* d_out, int out_size)
{
    const float* x  = (const float*)d_in[0];
    const float* Wi = (const float*)d_in[1];
    const float* bi = (const float*)d_in[2];
    const float* Wk = (const float*)d_in[3];
    const float* bk = (const float*)d_in[4];
    const float* Wq = (const float*)d_in[5];
    const float* bq = (const float*)d_in[6];
    const float* Wv = (const float*)d_in[7];
    const float* bv = (const float*)d_in[8];
    const float* Wo = (const float*)d_in[9];
    const float* bo = (const float*)d_in[10];
    float* out = (float*)d_out;

    bf16 *p_xhi, *p_xlo, *p_hhi, *p_hlo, *p_kqvhi, *p_kqvlo, *p_ahi, *p_alo, *p_whi, *p_wlo;
    float *p_bias;
    cudaGetSymbolAddress((void**)&p_xhi, g_xhi);
    cudaGetSymbolAddress((void**)&p_xlo, g_xlo);
    cudaGetSymbolAddress((void**)&p_hhi, g_hhi);
    cudaGetSymbolAddress((void**)&p_hlo, g_hlo);
    cudaGetSymbolAddress((void**)&p_kqvhi, g_kqvhi);
    cudaGetSymbolAddress((void**)&p_kqvlo, g_kqvlo);
    cudaGetSymbolAddress((void**)&p_ahi, g_ahi);
    cudaGetSymbolAddress((void**)&p_alo, g_alo);
    cudaGetSymbolAddress((void**)&p_whi, g_whi);
    cudaGetSymbolAddress((void**)&p_wlo, g_wlo);
    cudaGetSymbolAddress((void**)&p_bias, g_bias);

    cudaFuncSetAttribute(gemm_bf16x3, cudaFuncAttributeMaxDynamicSharedMemorySize, GEMM_SMEM);
    cudaFuncSetAttribute(flash_mma, cudaFuncAttributeMaxDynamicSharedMemorySize, FLASH_SMEM);

    prep_w<<<(NALL * DD + 255) / 256, 256>>>(Wi, bi, Wk, bk, Wq, bq, Wv, bv, Wo, bo);
    prep_x<<<(int)(((size_t)MT * DD + 255) / 256), 256>>>(x);

    // h = x @ Wi + bi  -> bf16 hi/lo
    {
        dim3 grid(DD / 128, MT / 128);
        gemm_bf16x3<<<grid, 256, GEMM_SMEM>>>(p_xhi, p_xlo, p_whi, p_wlo, p_bias,
                                              nullptr, p_hhi, p_hlo, DD, DD, 1);
    }
    // kqv = h @ Wkqv + bkqv -> bf16 hi/lo
    {
        dim3 grid(NKQV / 128, MT / 128);
        gemm_bf16x3<<<grid, 256, GEMM_SMEM>>>(p_hhi, p_hlo,
            p_whi + (size_t)DD * DD, p_wlo + (size_t)DD * DD, p_bias + DD,
            nullptr, p_kqvhi, p_kqvlo, DD, NKQV, 1);
    }
    // fused causal attention (tensor cores) -> attn bf16 hi/lo
    {
        dim3 grid(TT / 64, HH, BB);
        flash_mma<<<grid, 128, FLASH_SMEM>>>(p_kqvhi, p_kqvlo, p_ahi, p_alo);
    }
    // out = attn @ Wo + bo -> fp32 to d_out
    {
        dim3 grid(DD / 128, MT / 128);
        gemm_bf16x3<<<grid, 256, GEMM_SMEM>>>(p_ahi, p_alo,
            p_whi + (size_t)(4 * DD) * DD, p_wlo + (size_t)(4 * DD) * DD, p_bias + 4 * DD,
            out, nullptr, nullptr, DD, DD, 0);
    }
}

// round 9
// speedup vs baseline: 2.6532x; 1.1036x over previous
#include <cuda_runtime.h>
#include <cuda_bf16.h>
#include <cstdint>
#include <math.h>

// ---------------- problem constants ----------------
#define BB 32
#define TT 512
#define DD 1024
#define HH 16
#define HD 64
#define MT (BB*TT)          // 16384
#define NKQV (3*DD)         // 3072
#define NALL (5*DD)         // 5120 combined weight rows: [Wi | Wkqv | Wo], layout [N][K]

typedef __nv_bfloat16 bf16;
typedef __nv_bfloat162 bf162;

// ---------------- scratch (device globals; no cudaMalloc allowed) ----------
__device__ __align__(256) bf16 g_xhi[(size_t)MT*DD], g_xlo[(size_t)MT*DD];
__device__ __align__(256) bf16 g_kqvhi[(size_t)MT*NKQV], g_kqvlo[(size_t)MT*NKQV];
__device__ __align__(256) bf16 g_ahi[(size_t)MT*DD], g_alo[(size_t)MT*DD];
__device__ __align__(256) bf16 g_whi[(size_t)NALL*DD], g_wlo[(size_t)NALL*DD];
__device__ __align__(256) bf16 g_wihi[(size_t)DD*DD], g_wilo[(size_t)DD*DD];   // Wi natural [din][dout]
__device__ __align__(256) bf16 g_wchi[(size_t)NKQV*DD], g_wclo[(size_t)NKQV*DD]; // fused Wc^T [n][din]
__device__ __align__(256) float g_bias[NALL];
__device__ __align__(256) float g_bc[NKQV];     // fused bias: bi@Wkqv + bkqv
__device__ __align__(256) float g_zerob[DD];    // zero-initialized (never written)

// ---------------- PTX helpers (all sm_80-generic; no 'a' features) ---------
__device__ __forceinline__ uint32_t smem_u32(const void* p) {
    uint32_t a;
    asm("{ .reg .u64 t; cvta.to.shared.u64 t, %1; cvt.u32.u64 %0, t; }" : "=r"(a) : "l"(p));
    return a;
}
__device__ __forceinline__ void cp16(uint32_t dst, const void* src) {
    asm volatile("cp.async.cg.shared.global [%0], [%1], 16;" :: "r"(dst), "l"(src) : "memory");
}
#define CP_COMMIT() asm volatile("cp.async.commit_group;" ::: "memory")
#define CP_WAIT(N)  asm volatile("cp.async.wait_group %0;" :: "n"(N) : "memory")

__device__ __forceinline__ void ldsm4(uint32_t r[4], uint32_t addr) {
    asm volatile("ldmatrix.sync.aligned.m8n8.x4.shared.b16 {%0,%1,%2,%3}, [%4];"
        : "=r"(r[0]), "=r"(r[1]), "=r"(r[2]), "=r"(r[3]) : "r"(addr));
}
__device__ __forceinline__ void ldsm4t(uint32_t r[4], uint32_t addr) {
    asm volatile("ldmatrix.sync.aligned.m8n8.x4.trans.shared.b16 {%0,%1,%2,%3}, [%4];"
        : "=r"(r[0]), "=r"(r[1]), "=r"(r[2]), "=r"(r[3]) : "r"(addr));
}
__device__ __forceinline__ void mma_bf16(float c[4], const uint32_t a[4],
                                         uint32_t b0, uint32_t b1) {
    asm volatile("mma.sync.aligned.m16n8k16.row.col.f32.bf16.bf16.f32 "
        "{%0,%1,%2,%3}, {%4,%5,%6,%7}, {%8,%9}, {%0,%1,%2,%3};"
        : "+f"(c[0]), "+f"(c[1]), "+f"(c[2]), "+f"(c[3])
        : "r"(a[0]), "r"(a[1]), "r"(a[2]), "r"(a[3]), "r"(b0), "r"(b1));
}

__device__ __forceinline__ void split_bf16(float v, bf16& hi, bf16& lo) {
    hi = __float2bfloat16_rn(v);
    lo = __float2bfloat16_rn(v - __bfloat162float(hi));
}
__device__ __forceinline__ uint32_t pack_split(float e0, float e1, uint32_t& lopair) {
    bf16 h0, l0, h1, l1;
    split_bf16(e0, h0, l0);
    split_bf16(e1, h1, l1);
    uint32_t hp, lp;
    asm("mov.b32 %0, {%1,%2};" : "=r"(hp) : "h"(*(unsigned short*)&h0), "h"(*(unsigned short*)&h1));
    asm("mov.b32 %0, {%1,%2};" : "=r"(lp) : "h"(*(unsigned short*)&l0), "h"(*(unsigned short*)&l1));
    lopair = lp;
    return hp;
}

// ---------------- prep kernels ----------------
__global__ void prep_w(const float* __restrict__ Wi, const float* __restrict__ bi,
                       const float* __restrict__ Wk, const float* __restrict__ bk,
                       const float* __restrict__ Wq, const float* __restrict__ bq,
                       const float* __restrict__ Wv, const float* __restrict__ bv,
                       const float* __restrict__ Wo, const float* __restrict__ bo)
{
    int idx = blockIdx.x * blockDim.x + threadIdx.x;
    if (idx < NALL * DD) {
        int n = idx >> 10;
        int k = idx & 1023;
        float w;
        if (n < DD) {
            w = Wi[(size_t)k * DD + n];
        } else if (n < 4 * DD) {
            int m = n - DD;
            int sec = m >> 10;
            int mm = m & 1023;
            const float* W = (sec == 0) ? Wk : (sec == 1) ? Wq : Wv;
            w = W[(size_t)(mm >> 6) * (DD * HD) + (size_t)k * HD + (mm & 63)];
        } else {
            w = Wo[(size_t)k * DD + (n - 4 * DD)];
        }
        split_bf16(w, g_whi[idx], g_wlo[idx]);
    }
    // Wi natural layout [din][dout] (B-operand for the Wc fusion GEMM)
    if (idx < DD * DD) {
        split_bf16(Wi[idx], g_wihi[idx], g_wilo[idx]);
    }
    if (idx < NALL) {
        float b;
        if (idx < DD) b = bi[idx];
        else if (idx < 4 * DD) {
            int m = idx - DD;
            b = ((m >> 10) == 0 ? bk : ((m >> 10) == 1 ? bq : bv))[m & 1023];
        } else b = bo[idx - 4 * DD];
        g_bias[idx] = b;
    }
}

__global__ void prep_x(const float* __restrict__ x)
{
    size_t idx = (size_t)blockIdx.x * blockDim.x + threadIdx.x;
    if (idx < (size_t)MT * DD) {
        split_bf16(x[idx], g_xhi[idx], g_xlo[idx]);
    }
}

// fused bias: bc[n] = bkqv[n] + sum_k bi[k] * Wkqv_rep[n][k]
__global__ void prep_bc()
{
    int n = blockIdx.x * blockDim.x + threadIdx.x;
    if (n < NKQV) {
        const bf16* wh = g_whi + (size_t)(DD + n) * DD;
        const bf16* wl = g_wlo + (size_t)(DD + n) * DD;
        float s = 0.f;
        for (int k = 0; k < DD; k++)
            s += g_bias[k] * (__bfloat162float(wh[k]) + __bfloat162float(wl[k]));
        g_bc[n] = s + g_bias[DD + n];
    }
}

// ---------------- mma.sync 3xBF16 GEMM ----------------
// C[M,N] = A[M,K] @ B^T + bias, A split hi/lo [M][K], B split hi/lo [N][K].
// BM=128, BN=128, BK=32. 256 threads = 8 warps (2 m x 4 n), warp tile 64x32.
#define GSTRIDE 40
#define GREG    10240u
#define GBUF    40960u
#define GEMM_SMEM (2 * GBUF)

__global__ __launch_bounds__(256)
void gemm_bf16x3(const bf16* __restrict__ Ahi, const bf16* __restrict__ Alo,
                 const bf16* __restrict__ Bhi, const bf16* __restrict__ Blo,
                 const float* __restrict__ bias,
                 float* __restrict__ C0, bf16* __restrict__ Chi, bf16* __restrict__ Clo,
                 int K, int ldC, int mode)
{
    extern __shared__ char smg[];
    const uint32_t smb = smem_u32(smg);
    const int tid = threadIdx.x;
    const int lane = tid & 31;
    const int wid = tid >> 5;
    const int warp_m = wid >> 2;
    const int warp_n = wid & 3;
    const int bm = blockIdx.y * 128;
    const int bn = blockIdx.x * 128;

    const int r0 = tid >> 2;
    const int q0 = tid & 3;
    const size_t a_src0 = (size_t)(bm + r0) * K + q0 * 8;
    const size_t a_src1 = a_src0 + (size_t)64 * K;
    const size_t b_src0 = (size_t)(bn + r0) * K + q0 * 8;
    const size_t b_src1 = b_src0 + (size_t)64 * K;
    const uint32_t d0 = (uint32_t)(r0 * (GSTRIDE * 2) + q0 * 16);
    const uint32_t d1 = d0 + 64u * (GSTRIDE * 2);

    const int nchunks = K >> 5;

#define LOAD_TILES(c, buf) do { \
    const uint32_t bb = smb + (uint32_t)(buf) * GBUF; \
    const size_t ko = (size_t)(c) * 32; \
    cp16(bb + 0*GREG + d0, Ahi + a_src0 + ko); \
    cp16(bb + 0*GREG + d1, Ahi + a_src1 + ko); \
    cp16(bb + 1*GREG + d0, Alo + a_src0 + ko); \
    cp16(bb + 1*GREG + d1, Alo + a_src1 + ko); \
    cp16(bb + 2*GREG + d0, Bhi + b_src0 + ko); \
    cp16(bb + 2*GREG + d1, Bhi + b_src1 + ko); \
    cp16(bb + 3*GREG + d0, Blo + b_src0 + ko); \
    cp16(bb + 3*GREG + d1, Blo + b_src1 + ko); \
    CP_COMMIT(); \
} while (0)

    const int row_in = lane & 7;
    const int grp = lane >> 3;
    const int a_m = warp_m * 64 + (grp & 1) * 8 + row_in;
    const int a_k = (grp >> 1) * 8;
    const int b_n = warp_n * 32 + (grp >> 1) * 8 + row_in;
    const int b_k = (grp & 1) * 8;

    float c[4][4][4];
#pragma unroll
    for (int mi = 0; mi < 4; mi++)
#pragma unroll
        for (int ni = 0; ni < 4; ni++)
#pragma unroll
            for (int r = 0; r < 4; r++) c[mi][ni][r] = 0.f;

    LOAD_TILES(0, 0);

    for (int cc = 0; cc < nchunks; cc++) {
        if (cc + 1 < nchunks) {
            LOAD_TILES(cc + 1, (cc + 1) & 1);
            CP_WAIT(1);
        } else {
            CP_WAIT(0);
        }
        __syncthreads();

        const uint32_t bb = smb + (uint32_t)(cc & 1) * GBUF;
#pragma unroll
        for (int ks = 0; ks < 2; ks++) {
            const int kofs = ks * 16;
            uint32_t ah[4][4], al[4][4];
#pragma unroll
            for (int mi = 0; mi < 4; mi++) {
                uint32_t off = (uint32_t)(((a_m + mi * 16) * GSTRIDE + a_k + kofs) * 2);
                ldsm4(ah[mi], bb + 0 * GREG + off);
                ldsm4(al[mi], bb + 1 * GREG + off);
            }
            uint32_t bh[2][4], bl[2][4];
#pragma unroll
            for (int n2 = 0; n2 < 2; n2++) {
                uint32_t off = (uint32_t)(((b_n + n2 * 16) * GSTRIDE + b_k + kofs) * 2);
                ldsm4(bh[n2], bb + 2 * GREG + off);
                ldsm4(bl[n2], bb + 3 * GREG + off);
            }
#pragma unroll
            for (int mi = 0; mi < 4; mi++) {
#pragma unroll
                for (int ni = 0; ni < 4; ni++) {
                    const int n2 = ni >> 1, hb = (ni & 1) * 2;
                    mma_bf16(c[mi][ni], ah[mi], bh[n2][hb], bh[n2][hb + 1]);
                    mma_bf16(c[mi][ni], ah[mi], bl[n2][hb], bl[n2][hb + 1]);
                    mma_bf16(c[mi][ni], al[mi], bh[n2][hb], bh[n2][hb + 1]);
                }
            }
        }
        __syncthreads();
    }

    const int g = lane >> 2;
    const int t = lane & 3;
#pragma unroll
    for (int mi = 0; mi < 4; mi++) {
#pragma unroll
        for (int ni = 0; ni < 4; ni++) {
            const int col = bn + warp_n * 32 + ni * 8 + 2 * t;
            const float bx = bias[col], by = bias[col + 1];
            const int row0 = bm + warp_m * 64 + mi * 16 + g;
            const int row1 = row0 + 8;
            float v00 = c[mi][ni][0] + bx, v01 = c[mi][ni][1] + by;
            float v10 = c[mi][ni][2] + bx, v11 = c[mi][ni][3] + by;
            if (mode == 0) {
                *(float2*)(C0 + (size_t)row0 * ldC + col) = make_float2(v00, v01);
                *(float2*)(C0 + (size_t)row1 * ldC + col) = make_float2(v10, v11);
            } else {
                bf16 h0, l0, h1, l1;
                split_bf16(v00, h0, l0); split_bf16(v01, h1, l1);
                *(bf162*)(Chi + (size_t)row0 * ldC + col) = bf162(h0, h1);
                *(bf162*)(Clo + (size_t)row0 * ldC + col) = bf162(l0, l1);
                split_bf16(v10, h0, l0); split_bf16(v11, h1, l1);
                *(bf162*)(Chi + (size_t)row1 * ldC + col) = bf162(h0, h1);
                *(bf162*)(Clo + (size_t)row1 * ldC + col) = bf162(l0, l1);
            }
        }
    }
#undef LOAD_TILES
}

// ---------------- tensor-core causal flash attention (3xBF16) -------------
// Reference: wei[t,s] = k_t . q_s, causal mask, softmax over s, out = wei@v.
// Q := k-section (col 0), K := q-section (+1024), V := v-section (+2048).
#define QSTR 72
#define FA_ARR 9216u
#define FA_BUF0 18432u
#define FA_BUFSZ 36864u
#define FLASH_SMEM 92160

__global__ __launch_bounds__(128)
void flash_mma(const bf16* __restrict__ khi, const bf16* __restrict__ klo,
               bf16* __restrict__ outhi, bf16* __restrict__ outlo)
{
    extern __shared__ char smf[];
    const uint32_t smb = smem_u32(smf);
    const int tid = threadIdx.x;
    const int lane = tid & 31;
    const int warp = tid >> 5;
    const int grp = lane >> 3, row_in = lane & 7;
    const int g = lane >> 2, t = lane & 3;
    const int tt = blockIdx.x, h = blockIdx.y, b = blockIdx.z;

    const size_t bh = (size_t)(b * TT) * NKQV + h * HD;
    const int ldrow = tid >> 1;
    const int ldhc = (tid & 1) * 32;

    {
        const bf16* s0 = khi + bh + (size_t)(tt * 64 + ldrow) * NKQV + ldhc;
        const bf16* s1 = klo + bh + (size_t)(tt * 64 + ldrow) * NKQV + ldhc;
        uint32_t d = smb + (uint32_t)(ldrow * QSTR + ldhc) * 2;
        cp16(d, s0); cp16(d + 16, s0 + 8); cp16(d + 32, s0 + 16); cp16(d + 48, s0 + 24);
        d += FA_ARR;
        cp16(d, s1); cp16(d + 16, s1 + 8); cp16(d + 32, s1 + 16); cp16(d + 48, s1 + 24);
    }

#define FA_LOAD_KV(st, buf) do { \
    size_t gofs = bh + (size_t)((st) * 64 + ldrow) * NKQV + ldhc; \
    uint32_t base = smb + FA_BUF0 + (uint32_t)(buf) * FA_BUFSZ + (uint32_t)(ldrow * QSTR + ldhc) * 2; \
    const bf16* p0 = khi + gofs + 1024; \
    cp16(base + 0 * FA_ARR, p0); cp16(base + 0 * FA_ARR + 16, p0 + 8); \
    cp16(base + 0 * FA_ARR + 32, p0 + 16); cp16(base + 0 * FA_ARR + 48, p0 + 24); \
    const bf16* p1 = klo + gofs + 1024; \
    cp16(base + 1 * FA_ARR, p1); cp16(base + 1 * FA_ARR + 16, p1 + 8); \
    cp16(base + 1 * FA_ARR + 32, p1 + 16); cp16(base + 1 * FA_ARR + 48, p1 + 24); \
    const bf16* p2 = khi + gofs + 2048; \
    cp16(base + 2 * FA_ARR, p2); cp16(base + 2 * FA_ARR + 16, p2 + 8); \
    cp16(base + 2 * FA_ARR + 32, p2 + 16); cp16(base + 2 * FA_ARR + 48, p2 + 24); \
    const bf16* p3 = klo + gofs + 2048; \
    cp16(base + 3 * FA_ARR, p3); cp16(base + 3 * FA_ARR + 16, p3 + 8); \
    cp16(base + 3 * FA_ARR + 32, p3 + 16); cp16(base + 3 * FA_ARR + 48, p3 + 24); \
} while (0)

    FA_LOAD_KV(0, 0);
    CP_COMMIT();

    float m_r[2] = { -1e30f, -1e30f };
    float l_r[2] = { 0.f, 0.f };
    float o[8][4];
#pragma unroll
    for (int ei = 0; ei < 8; ei++)
#pragma unroll
        for (int r = 0; r < 4; r++) o[ei][r] = 0.f;

    uint32_t qh[4][4], ql[4][4];

    const int a_m = warp * 16 + (grp & 1) * 8 + row_in;
    const int a_k = (grp >> 1) * 8;
    const int b_n = (grp >> 1) * 8 + row_in;
    const int b_k = (grp & 1) * 8;
    const int v_s = (grp & 1) * 8 + row_in;
    const int v_e = (grp >> 1) * 8;

    for (int st = 0; st <= tt; st++) {
        if (st < tt) {
            FA_LOAD_KV(st + 1, (st + 1) & 1);
            CP_COMMIT();
            CP_WAIT(1);
        } else {
            CP_WAIT(0);
        }
        __syncthreads();

        if (st == 0) {
#pragma unroll
            for (int kc = 0; kc < 4; kc++) {
                uint32_t off = (uint32_t)((a_m * QSTR + a_k + kc * 16) * 2);
                ldsm4(qh[kc], smb + off);
                ldsm4(ql[kc], smb + FA_ARR + off);
            }
        }

        const uint32_t kb = smb + FA_BUF0 + (uint32_t)(st & 1) * FA_BUFSZ;

        float sc[8][4];
#pragma unroll
        for (int ni = 0; ni < 8; ni++)
#pragma unroll
            for (int r = 0; r < 4; r++) sc[ni][r] = 0.f;

#pragma unroll
        for (int kc = 0; kc < 4; kc++) {
            uint32_t kh[4][4], kl[4][4];
#pragma unroll
            for (int j = 0; j < 4; j++) {
                uint32_t off = (uint32_t)(((b_n + j * 16) * QSTR + b_k + kc * 16) * 2);
                ldsm4(kh[j], kb + 0 * FA_ARR + off);
                ldsm4(kl[j], kb + 1 * FA_ARR + off);
            }
#pragma unroll
            for (int j = 0; j < 4; j++) {
                mma_bf16(sc[2 * j],     qh[kc], kh[j][0], kh[j][1]);
                mma_bf16(sc[2 * j],     qh[kc], kl[j][0], kl[j][1]);
                mma_bf16(sc[2 * j],     ql[kc], kh[j][0], kh[j][1]);
                mma_bf16(sc[2 * j + 1], qh[kc], kh[j][2], kh[j][3]);
                mma_bf16(sc[2 * j + 1], qh[kc], kl[j][2], kl[j][3]);
                mma_bf16(sc[2 * j + 1], ql[kc], kh[j][2], kh[j][3]);
            }
        }

        if (st == tt) {
#pragma unroll
            for (int ni = 0; ni < 8; ni++) {
                int c0 = ni * 8 + 2 * t, c1 = c0 + 1;
                int r0 = warp * 16 + g, r1 = r0 + 8;
                if (c0 > r0) sc[ni][0] = -1e30f;
                if (c1 > r0) sc[ni][1] = -1e30f;
                if (c0 > r1) sc[ni][2] = -1e30f;
                if (c1 > r1) sc[ni][3] = -1e30f;
            }
        }

        float mloc0 = -1e30f, mloc1 = -1e30f;
#pragma unroll
        for (int ni = 0; ni < 8; ni++) {
            mloc0 = fmaxf(mloc0, fmaxf(sc[ni][0], sc[ni][1]));
            mloc1 = fmaxf(mloc1, fmaxf(sc[ni][2], sc[ni][3]));
        }
#pragma unroll
        for (int off = 1; off < 4; off <<= 1) {
            mloc0 = fmaxf(mloc0, __shfl_xor_sync(0xffffffffu, mloc0, off));
            mloc1 = fmaxf(mloc1, __shfl_xor_sync(0xffffffffu, mloc1, off));
        }
        float mnew0 = fmaxf(m_r[0], mloc0);
        float mnew1 = fmaxf(m_r[1], mloc1);
        float scale0 = __expf(m_r[0] - mnew0);
        float scale1 = __expf(m_r[1] - mnew1);
        m_r[0] = mnew0; m_r[1] = mnew1;

        float ls0 = 0.f, ls1 = 0.f;
#pragma unroll
        for (int ni = 0; ni < 8; ni++) {
            sc[ni][0] = __expf(sc[ni][0] - mnew0);
            sc[ni][1] = __expf(sc[ni][1] - mnew0);
            sc[ni][2] = __expf(sc[ni][2] - mnew1);
            sc[ni][3] = __expf(sc[ni][3] - mnew1);
            ls0 += sc[ni][0] + sc[ni][1];
            ls1 += sc[ni][2] + sc[ni][3];
        }
#pragma unroll
        for (int off = 1; off < 4; off <<= 1) {
            ls0 += __shfl_xor_sync(0xffffffffu, ls0, off);
            ls1 += __shfl_xor_sync(0xffffffffu, ls1, off);
        }
        l_r[0] = l_r[0] * scale0 + ls0;
        l_r[1] = l_r[1] * scale1 + ls1;

#pragma unroll
        for (int ei = 0; ei < 8; ei++) {
            o[ei][0] *= scale0; o[ei][1] *= scale0;
            o[ei][2] *= scale1; o[ei][3] *= scale1;
        }

#pragma unroll
        for (int kc = 0; kc < 4; kc++) {
            uint32_t pa_h[4], pa_l[4];
            pa_h[0] = pack_split(sc[2 * kc][0],     sc[2 * kc][1],     pa_l[0]);
            pa_h[1] = pack_split(sc[2 * kc][2],     sc[2 * kc][3],     pa_l[1]);
            pa_h[2] = pack_split(sc[2 * kc + 1][0], sc[2 * kc + 1][1], pa_l[2]);
            pa_h[3] = pack_split(sc[2 * kc + 1][2], sc[2 * kc + 1][3], pa_l[3]);

            uint32_t vh[4][4], vl[4][4];
#pragma unroll
            for (int j = 0; j < 4; j++) {
                uint32_t off = (uint32_t)(((kc * 16 + v_s) * QSTR + j * 16 + v_e) * 2);
                ldsm4t(vh[j], kb + 2 * FA_ARR + off);
                ldsm4t(vl[j], kb + 3 * FA_ARR + off);
            }
#pragma unroll
            for (int j = 0; j < 4; j++) {
                mma_bf16(o[2 * j],     pa_h, vh[j][0], vh[j][1]);
                mma_bf16(o[2 * j],     pa_h, vl[j][0], vl[j][1]);
                mma_bf16(o[2 * j],     pa_l, vh[j][0], vh[j][1]);
                mma_bf16(o[2 * j + 1], pa_h, vh[j][2], vh[j][3]);
                mma_bf16(o[2 * j + 1], pa_h, vl[j][2], vl[j][3]);
                mma_bf16(o[2 * j + 1], pa_l, vh[j][2], vh[j][3]);
            }
        }
        __syncthreads();
    }

    const float inv0 = 1.f / l_r[0];
    const float inv1 = 1.f / l_r[1];
    const size_t r0 = (size_t)(b * TT + tt * 64 + warp * 16 + g);
    const size_t r1 = r0 + 8;
#pragma unroll
    for (int ei = 0; ei < 8; ei++) {
        const int col = h * HD + ei * 8 + 2 * t;
        bf16 h0, l0, h1, l1;
        split_bf16(o[ei][0] * inv0, h0, l0);
        split_bf16(o[ei][1] * inv0, h1, l1);
        *(bf162*)(outhi + r0 * DD + col) = bf162(h0, h1);
        *(bf162*)(outlo + r0 * DD + col) = bf162(l0, l1);
        split_bf16(o[ei][2] * inv1, h0, l0);
        split_bf16(o[ei][3] * inv1, h1, l1);
        *(bf162*)(outhi + r1 * DD + col) = bf162(h0, h1);
        *(bf162*)(outlo + r1 * DD + col) = bf162(l0, l1);
    }
#undef FA_LOAD_KV
}

// ---------------- launch ----------------
extern "C" void kernel_launch(void* const* d_in, const int* in_sizes, int n_in,
                              void* d_out, int out_size)
{
    const float* x  = (const float*)d_in[0];
    const float* Wi = (const float*)d_in[1];
    const float* bi = (const float*)d_in[2];
    const float* Wk = (const float*)d_in[3];
    const float* bk = (const float*)d_in[4];
    const float* Wq = (const float*)d_in[5];
    const float* bq = (const float*)d_in[6];
    const float* Wv = (const float*)d_in[7];
    const float* bv = (const float*)d_in[8];
    const float* Wo = (const float*)d_in[9];
    const float* bo = (const float*)d_in[10];
    float* out = (float*)d_out;

    bf16 *p_xhi, *p_xlo, *p_kqvhi, *p_kqvlo, *p_ahi, *p_alo, *p_whi, *p_wlo;
    bf16 *p_wihi, *p_wilo, *p_wchi, *p_wclo;
    float *p_bias, *p_bc, *p_zerob;
    cudaGetSymbolAddress((void**)&p_xhi, g_xhi);
    cudaGetSymbolAddress((void**)&p_xlo, g_xlo);
    cudaGetSymbolAddress((void**)&p_kqvhi, g_kqvhi);
    cudaGetSymbolAddress((void**)&p_kqvlo, g_kqvlo);
    cudaGetSymbolAddress((void**)&p_ahi, g_ahi);
    cudaGetSymbolAddress((void**)&p_alo, g_alo);
    cudaGetSymbolAddress((void**)&p_whi, g_whi);
    cudaGetSymbolAddress((void**)&p_wlo, g_wlo);
    cudaGetSymbolAddress((void**)&p_wihi, g_wihi);
    cudaGetSymbolAddress((void**)&p_wilo, g_wilo);
    cudaGetSymbolAddress((void**)&p_wchi, g_wchi);
    cudaGetSymbolAddress((void**)&p_wclo, g_wclo);
    cudaGetSymbolAddress((void**)&p_bias, g_bias);
    cudaGetSymbolAddress((void**)&p_bc, g_bc);
    cudaGetSymbolAddress((void**)&p_zerob, g_zerob);

    cudaFuncSetAttribute(gemm_bf16x3, cudaFuncAttributeMaxDynamicSharedMemorySize, GEMM_SMEM);
    cudaFuncSetAttribute(flash_mma, cudaFuncAttributeMaxDynamicSharedMemorySize, FLASH_SMEM);

    prep_w<<<(NALL * DD + 255) / 256, 256>>>(Wi, bi, Wk, bk, Wq, bq, Wv, bv, Wo, bo);
    prep_x<<<(int)(((size_t)MT * DD + 255) / 256), 256>>>(x);

    // Wc^T[n][din] = sum_k Wkqv_rep[n][k] * Wi[din][k]   (fused Wi@Wkqv), bf16 hi/lo out
    {
        dim3 grid(DD / 128, NKQV / 128);
        gemm_bf16x3<<<grid, 256, GEMM_SMEM>>>(
            p_whi + (size_t)DD * DD, p_wlo + (size_t)DD * DD,
            p_wihi, p_wilo, p_zerob,
            nullptr, p_wchi, p_wclo, DD, DD, 1);
    }
    // bc = bi @ Wkqv + bkqv
    prep_bc<<<(NKQV + 255) / 256, 256>>>();

    // kqv = x @ Wc^T + bc -> bf16 hi/lo  (h GEMM eliminated by fusion)
    {
        dim3 grid(NKQV / 128, MT / 128);
        gemm_bf16x3<<<grid, 256, GEMM_SMEM>>>(p_xhi, p_xlo,
            p_wchi, p_wclo, p_bc,
            nullptr, p_kqvhi, p_kqvlo, DD, NKQV, 1);
    }
    // fused causal attention (tensor cores) -> attn bf16 hi/lo
    {
        dim3 grid(TT / 64, HH, BB);
        flash_mma<<<grid, 128, FLASH_SMEM>>>(p_kqvhi, p_kqvlo, p_ahi, p_alo);
    }
    // out = attn @ Wo + bo -> fp32 to d_out
    {
        dim3 grid(DD / 128, MT / 128);
        gemm_bf16x3<<<grid, 256, GEMM_SMEM>>>(p_ahi, p_alo,
            p_whi + (size_t)(4 * DD) * DD, p_wlo + (size_t)(4 * DD) * DD, p_bias + 4 * DD,
            out, nullptr, nullptr, DD, DD, 0);
    }
}

// round 13
// speedup vs baseline: 2.7980x; 1.0546x over previous
#include <cuda_runtime.h>
#include <cuda_bf16.h>
#include <cstdint>
#include <math.h>

// ---------------- problem constants ----------------
#define BB 32
#define TT 512
#define DD 1024
#define HH 16
#define HD 64
#define MT (BB*TT)          // 16384
#define NKQV (3*DD)         // 3072
#define NALL (5*DD)         // 5120 combined weight rows: [unused | Wkqv | Wo], layout [N][K]

typedef __nv_bfloat16 bf16;
typedef __nv_bfloat162 bf162;

// ---------------- scratch (device globals; no cudaMalloc allowed) ----------
__device__ __align__(256) bf16 g_xhi[(size_t)MT*DD], g_xlo[(size_t)MT*DD];
__device__ __align__(256) bf16 g_kqvhi[(size_t)MT*NKQV], g_kqvlo[(size_t)MT*NKQV];
__device__ __align__(256) bf16 g_ahi[(size_t)MT*DD], g_alo[(size_t)MT*DD];
__device__ __align__(256) bf16 g_whi[(size_t)NALL*DD], g_wlo[(size_t)NALL*DD];
__device__ __align__(256) bf16 g_wihi[(size_t)DD*DD], g_wilo[(size_t)DD*DD];   // Wi natural [din][dout]
__device__ __align__(256) bf16 g_wchi[(size_t)NKQV*DD], g_wclo[(size_t)NKQV*DD]; // fused Wc^T [n][din]
__device__ __align__(256) float g_bias[NALL];
__device__ __align__(256) float g_bc[NKQV];     // fused bias: bi@Wkqv + bkqv
__device__ __align__(256) float g_zerob[DD];    // zero-initialized (never written)

// ---------------- PTX helpers (all sm_80-generic; no 'a' features) ---------
__device__ __forceinline__ uint32_t smem_u32(const void* p) {
    uint32_t a;
    asm("{ .reg .u64 t; cvta.to.shared.u64 t, %1; cvt.u32.u64 %0, t; }" : "=r"(a) : "l"(p));
    return a;
}
__device__ __forceinline__ void cp16(uint32_t dst, const void* src) {
    asm volatile("cp.async.cg.shared.global [%0], [%1], 16;" :: "r"(dst), "l"(src) : "memory");
}
#define CP_COMMIT() asm volatile("cp.async.commit_group;" ::: "memory")
#define CP_WAIT(N)  asm volatile("cp.async.wait_group %0;" :: "n"(N) : "memory")

__device__ __forceinline__ void ldsm4(uint32_t r[4], uint32_t addr) {
    asm volatile("ldmatrix.sync.aligned.m8n8.x4.shared.b16 {%0,%1,%2,%3}, [%4];"
        : "=r"(r[0]), "=r"(r[1]), "=r"(r[2]), "=r"(r[3]) : "r"(addr));
}
__device__ __forceinline__ void ldsm4t(uint32_t r[4], uint32_t addr) {
    asm volatile("ldmatrix.sync.aligned.m8n8.x4.trans.shared.b16 {%0,%1,%2,%3}, [%4];"
        : "=r"(r[0]), "=r"(r[1]), "=r"(r[2]), "=r"(r[3]) : "r"(addr));
}
__device__ __forceinline__ void mma_bf16(float c[4], const uint32_t a[4],
                                         uint32_t b0, uint32_t b1) {
    asm volatile("mma.sync.aligned.m16n8k16.row.col.f32.bf16.bf16.f32 "
        "{%0,%1,%2,%3}, {%4,%5,%6,%7}, {%8,%9}, {%0,%1,%2,%3};"
        : "+f"(c[0]), "+f"(c[1]), "+f"(c[2]), "+f"(c[3])
        : "r"(a[0]), "r"(a[1]), "r"(a[2]), "r"(a[3]), "r"(b0), "r"(b1));
}

__device__ __forceinline__ void split_bf16(float v, bf16& hi, bf16& lo) {
    hi = __float2bfloat16_rn(v);
    lo = __float2bfloat16_rn(v - __bfloat162float(hi));
}
__device__ __forceinline__ uint32_t pack_split(float e0, float e1, uint32_t& lopair) {
    bf16 h0, l0, h1, l1;
    split_bf16(e0, h0, l0);
    split_bf16(e1, h1, l1);
    uint32_t hp, lp;
    asm("mov.b32 %0, {%1,%2};" : "=r"(hp) : "h"(*(unsigned short*)&h0), "h"(*(unsigned short*)&h1));
    asm("mov.b32 %0, {%1,%2};" : "=r"(lp) : "h"(*(unsigned short*)&l0), "h"(*(unsigned short*)&l1));
    lopair = lp;
    return hp;
}

// ---------------- prep kernels (all coalesced) ----------------
__global__ void prep_bias(const float* __restrict__ bi, const float* __restrict__ bk,
                          const float* __restrict__ bq, const float* __restrict__ bv,
                          const float* __restrict__ bo)
{
    int idx = blockIdx.x * blockDim.x + threadIdx.x;
    if (idx < NALL) {
        float b;
        if (idx < DD) b = bi[idx];
        else if (idx < 4 * DD) {
            int m = idx - DD;
            b = ((m >> 10) == 0 ? bk : ((m >> 10) == 1 ? bq : bv))[m & 1023];
        } else b = bo[idx - 4 * DD];
        g_bias[idx] = b;
    }
}

// Wi natural [din][dout] split (coalesced float4)
__global__ void prep_wi(const float* __restrict__ Wi)
{
    size_t i4 = (size_t)blockIdx.x * blockDim.x + threadIdx.x;
    if (i4 < (size_t)DD * DD / 4) {
        float4 v = ((const float4*)Wi)[i4];
        bf16 h0,l0,h1,l1,h2,l2,h3,l3;
        split_bf16(v.x,h0,l0); split_bf16(v.y,h1,l1);
        split_bf16(v.z,h2,l2); split_bf16(v.w,h3,l3);
        ((bf162*)g_wihi)[i4*2]   = bf162(h0,h1);
        ((bf162*)g_wihi)[i4*2+1] = bf162(h2,h3);
        ((bf162*)g_wilo)[i4*2]   = bf162(l0,l1);
        ((bf162*)g_wilo)[i4*2+1] = bf162(l2,l3);
    }
}

// Wkqv repack: W[h][d][e] -> g_whi[DD + sec*1024 + h*64 + e][d], smem-tiled transpose
// grid (DD/32=32, HD/32=2, 48=3sec*16h), block (32, 8)
__global__ void prep_wkqv_t(const float* __restrict__ Wk, const float* __restrict__ Wq,
                            const float* __restrict__ Wv)
{
    __shared__ float tile[32][33];
    const int z = blockIdx.z;
    const int sec = z >> 4, h = z & 15;
    const float* src = (sec == 0 ? Wk : sec == 1 ? Wq : Wv) + (size_t)h * DD * HD;
    const int d0 = blockIdx.x * 32;
    const int e0 = blockIdx.y * 32;
    const int tx = threadIdx.x;
#pragma unroll
    for (int i = threadIdx.y; i < 32; i += 8)
        tile[i][tx] = src[(size_t)(d0 + i) * HD + e0 + tx];
    __syncthreads();
#pragma unroll
    for (int i = threadIdx.y; i < 32; i += 8) {
        float v = tile[tx][i];   // = src[d0+tx][e0+i]
        int n = DD + sec * 1024 + h * 64 + e0 + i;
        size_t o = (size_t)n * DD + d0 + tx;
        bf16 hi, lo; split_bf16(v, hi, lo);
        g_whi[o] = hi; g_wlo[o] = lo;
    }
}

// Wo repack: Wo[k][n] -> g_whi[4*DD + n][k], smem-tiled transpose
// grid (32, 32), block (32, 8)
__global__ void prep_wo_t(const float* __restrict__ Wo)
{
    __shared__ float tile[32][33];
    const int k0 = blockIdx.x * 32;
    const int n0 = blockIdx.y * 32;
    const int tx = threadIdx.x;
#pragma unroll
    for (int i = threadIdx.y; i < 32; i += 8)
        tile[i][tx] = Wo[(size_t)(k0 + i) * DD + n0 + tx];
    __syncthreads();
#pragma unroll
    for (int i = threadIdx.y; i < 32; i += 8) {
        float v = tile[tx][i];   // = Wo[k0+tx][n0+i]
        size_t o = (size_t)(4 * DD + n0 + i) * DD + k0 + tx;
        bf16 hi, lo; split_bf16(v, hi, lo);
        g_whi[o] = hi; g_wlo[o] = lo;
    }
}

__global__ void prep_x(const float* __restrict__ x)
{
    size_t i4 = (size_t)blockIdx.x * blockDim.x + threadIdx.x;
    if (i4 < (size_t)MT * DD / 4) {
        float4 v = ((const float4*)x)[i4];
        bf16 h0,l0,h1,l1,h2,l2,h3,l3;
        split_bf16(v.x,h0,l0); split_bf16(v.y,h1,l1);
        split_bf16(v.z,h2,l2); split_bf16(v.w,h3,l3);
        ((bf162*)g_xhi)[i4*2]   = bf162(h0,h1);
        ((bf162*)g_xhi)[i4*2+1] = bf162(h2,h3);
        ((bf162*)g_xlo)[i4*2]   = bf162(l0,l1);
        ((bf162*)g_xlo)[i4*2+1] = bf162(l2,l3);
    }
}

// fused bias: bc[n] = bkqv[n] + sum_k bi[k]*Wkqv_rep[n][k]  (warp per n)
__global__ void prep_bc()
{
    int gw = (blockIdx.x * blockDim.x + threadIdx.x) >> 5;
    int lane = threadIdx.x & 31;
    if (gw < NKQV) {
        const bf16* wh = g_whi + (size_t)(DD + gw) * DD;
        const bf16* wl = g_wlo + (size_t)(DD + gw) * DD;
        float s = 0.f;
        for (int k = lane; k < DD; k += 32)
            s += g_bias[k] * (__bfloat162float(wh[k]) + __bfloat162float(wl[k]));
#pragma unroll
        for (int off = 16; off > 0; off >>= 1)
            s += __shfl_xor_sync(0xffffffffu, s, off);
        if (lane == 0) g_bc[gw] = s + g_bias[DD + gw];
    }
}

// ---------------- mma.sync 3xBF16 GEMM ----------------
// C[M,N] = A[M,K] @ B^T + bias, A split hi/lo [M][K], B split hi/lo [N][K].
// BM=128, BN=128, BK=32. 256 threads = 8 warps (2 m x 4 n), warp tile 64x32.
#define GSTRIDE 40
#define GREG    10240u
#define GBUF    40960u
#define GEMM_SMEM (2 * GBUF)

__global__ __launch_bounds__(256)
void gemm_bf16x3(const bf16* __restrict__ Ahi, const bf16* __restrict__ Alo,
                 const bf16* __restrict__ Bhi, const bf16* __restrict__ Blo,
                 const float* __restrict__ bias,
                 float* __restrict__ C0, bf16* __restrict__ Chi, bf16* __restrict__ Clo,
                 int K, int ldC, int mode)
{
    extern __shared__ char smg[];
    const uint32_t smb = smem_u32(smg);
    const int tid = threadIdx.x;
    const int lane = tid & 31;
    const int wid = tid >> 5;
    const int warp_m = wid >> 2;
    const int warp_n = wid & 3;
    const int bm = blockIdx.y * 128;
    const int bn = blockIdx.x * 128;

    const int r0 = tid >> 2;
    const int q0 = tid & 3;
    const size_t a_src0 = (size_t)(bm + r0) * K + q0 * 8;
    const size_t a_src1 = a_src0 + (size_t)64 * K;
    const size_t b_src0 = (size_t)(bn + r0) * K + q0 * 8;
    const size_t b_src1 = b_src0 + (size_t)64 * K;
    const uint32_t d0 = (uint32_t)(r0 * (GSTRIDE * 2) + q0 * 16);
    const uint32_t d1 = d0 + 64u * (GSTRIDE * 2);

    const int nchunks = K >> 5;

#define LOAD_TILES(c, buf) do { \
    const uint32_t bb = smb + (uint32_t)(buf) * GBUF; \
    const size_t ko = (size_t)(c) * 32; \
    cp16(bb + 0*GREG + d0, Ahi + a_src0 + ko); \
    cp16(bb + 0*GREG + d1, Ahi + a_src1 + ko); \
    cp16(bb + 1*GREG + d0, Alo + a_src0 + ko); \
    cp16(bb + 1*GREG + d1, Alo + a_src1 + ko); \
    cp16(bb + 2*GREG + d0, Bhi + b_src0 + ko); \
    cp16(bb + 2*GREG + d1, Bhi + b_src1 + ko); \
    cp16(bb + 3*GREG + d0, Blo + b_src0 + ko); \
    cp16(bb + 3*GREG + d1, Blo + b_src1 + ko); \
    CP_COMMIT(); \
} while (0)

    const int row_in = lane & 7;
    const int grp = lane >> 3;
    const int a_m = warp_m * 64 + (grp & 1) * 8 + row_in;
    const int a_k = (grp >> 1) * 8;
    const int b_n = warp_n * 32 + (grp >> 1) * 8 + row_in;
    const int b_k = (grp & 1) * 8;

    float c[4][4][4];
#pragma unroll
    for (int mi = 0; mi < 4; mi++)
#pragma unroll
        for (int ni = 0; ni < 4; ni++)
#pragma unroll
            for (int r = 0; r < 4; r++) c[mi][ni][r] = 0.f;

    LOAD_TILES(0, 0);

    for (int cc = 0; cc < nchunks; cc++) {
        if (cc + 1 < nchunks) {
            LOAD_TILES(cc + 1, (cc + 1) & 1);
            CP_WAIT(1);
        } else {
            CP_WAIT(0);
        }
        __syncthreads();

        const uint32_t bb = smb + (uint32_t)(cc & 1) * GBUF;
#pragma unroll
        for (int ks = 0; ks < 2; ks++) {
            const int kofs = ks * 16;
            uint32_t ah[4][4], al[4][4];
#pragma unroll
            for (int mi = 0; mi < 4; mi++) {
                uint32_t off = (uint32_t)(((a_m + mi * 16) * GSTRIDE + a_k + kofs) * 2);
                ldsm4(ah[mi], bb + 0 * GREG + off);
                ldsm4(al[mi], bb + 1 * GREG + off);
            }
            uint32_t bh[2][4], bl[2][4];
#pragma unroll
            for (int n2 = 0; n2 < 2; n2++) {
                uint32_t off = (uint32_t)(((b_n + n2 * 16) * GSTRIDE + b_k + kofs) * 2);
                ldsm4(bh[n2], bb + 2 * GREG + off);
                ldsm4(bl[n2], bb + 3 * GREG + off);
            }
            // three passes -> no back-to-back RAW on any accumulator
#pragma unroll
            for (int mi = 0; mi < 4; mi++)
#pragma unroll
                for (int ni = 0; ni < 4; ni++) {
                    const int n2 = ni >> 1, hb = (ni & 1) * 2;
                    mma_bf16(c[mi][ni], ah[mi], bh[n2][hb], bh[n2][hb + 1]);
                }
#pragma unroll
            for (int mi = 0; mi < 4; mi++)
#pragma unroll
                for (int ni = 0; ni < 4; ni++) {
                    const int n2 = ni >> 1, hb = (ni & 1) * 2;
                    mma_bf16(c[mi][ni], ah[mi], bl[n2][hb], bl[n2][hb + 1]);
                }
#pragma unroll
            for (int mi = 0; mi < 4; mi++)
#pragma unroll
                for (int ni = 0; ni < 4; ni++) {
                    const int n2 = ni >> 1, hb = (ni & 1) * 2;
                    mma_bf16(c[mi][ni], al[mi], bh[n2][hb], bh[n2][hb + 1]);
                }
        }
        __syncthreads();
    }

    const int g = lane >> 2;
    const int t = lane & 3;
#pragma unroll
    for (int mi = 0; mi < 4; mi++) {
#pragma unroll
        for (int ni = 0; ni < 4; ni++) {
            const int col = bn + warp_n * 32 + ni * 8 + 2 * t;
            const float bx = bias[col], by = bias[col + 1];
            const int row0 = bm + warp_m * 64 + mi * 16 + g;
            const int row1 = row0 + 8;
            float v00 = c[mi][ni][0] + bx, v01 = c[mi][ni][1] + by;
            float v10 = c[mi][ni][2] + bx, v11 = c[mi][ni][3] + by;
            if (mode == 0) {
                *(float2*)(C0 + (size_t)row0 * ldC + col) = make_float2(v00, v01);
                *(float2*)(C0 + (size_t)row1 * ldC + col) = make_float2(v10, v11);
            } else {
                bf16 h0, l0, h1, l1;
                split_bf16(v00, h0, l0); split_bf16(v01, h1, l1);
                *(bf162*)(Chi + (size_t)row0 * ldC + col) = bf162(h0, h1);
                *(bf162*)(Clo + (size_t)row0 * ldC + col) = bf162(l0, l1);
                split_bf16(v10, h0, l0); split_bf16(v11, h1, l1);
                *(bf162*)(Chi + (size_t)row1 * ldC + col) = bf162(h0, h1);
                *(bf162*)(Clo + (size_t)row1 * ldC + col) = bf162(l0, l1);
            }
        }
    }
#undef LOAD_TILES
}

// ---------------- tensor-core causal flash attention (3xBF16) -------------
// Reference: wei[t,s] = k_t . q_s, causal mask, softmax over s, out = wei@v.
// Q := k-section (col 0), K := q-section (+1024), V := v-section (+2048).
#define QSTR 72
#define FA_ARR 9216u
#define FA_BUF0 18432u
#define FA_BUFSZ 36864u
#define FLASH_SMEM 92160

__global__ __launch_bounds__(128)
void flash_mma(const bf16* __restrict__ khi, const bf16* __restrict__ klo,
               bf16* __restrict__ outhi, bf16* __restrict__ outlo)
{
    extern __shared__ char smf[];
    const uint32_t smb = smem_u32(smf);
    const int tid = threadIdx.x;
    const int lane = tid & 31;
    const int warp = tid >> 5;
    const int grp = lane >> 3, row_in = lane & 7;
    const int g = lane >> 2, t = lane & 3;
    const int tt = blockIdx.x, h = blockIdx.y, b = blockIdx.z;

    const size_t bh = (size_t)(b * TT) * NKQV + h * HD;
    const int ldrow = tid >> 1;
    const int ldhc = (tid & 1) * 32;

    {
        const bf16* s0 = khi + bh + (size_t)(tt * 64 + ldrow) * NKQV + ldhc;
        const bf16* s1 = klo + bh + (size_t)(tt * 64 + ldrow) * NKQV + ldhc;
        uint32_t d = smb + (uint32_t)(ldrow * QSTR + ldhc) * 2;
        cp16(d, s0); cp16(d + 16, s0 + 8); cp16(d + 32, s0 + 16); cp16(d + 48, s0 + 24);
        d += FA_ARR;
        cp16(d, s1); cp16(d + 16, s1 + 8); cp16(d + 32, s1 + 16); cp16(d + 48, s1 + 24);
    }

#define FA_LOAD_KV(st, buf) do { \
    size_t gofs = bh + (size_t)((st) * 64 + ldrow) * NKQV + ldhc; \
    uint32_t base = smb + FA_BUF0 + (uint32_t)(buf) * FA_BUFSZ + (uint32_t)(ldrow * QSTR + ldhc) * 2; \
    const bf16* p0 = khi + gofs + 1024; \
    cp16(base + 0 * FA_ARR, p0); cp16(base + 0 * FA_ARR + 16, p0 + 8); \
    cp16(base + 0 * FA_ARR + 32, p0 + 16); cp16(base + 0 * FA_ARR + 48, p0 + 24); \
    const bf16* p1 = klo + gofs + 1024; \
    cp16(base + 1 * FA_ARR, p1); cp16(base + 1 * FA_ARR + 16, p1 + 8); \
    cp16(base + 1 * FA_ARR + 32, p1 + 16); cp16(base + 1 * FA_ARR + 48, p1 + 24); \
    const bf16* p2 = khi + gofs + 2048; \
    cp16(base + 2 * FA_ARR, p2); cp16(base + 2 * FA_ARR + 16, p2 + 8); \
    cp16(base + 2 * FA_ARR + 32, p2 + 16); cp16(base + 2 * FA_ARR + 48, p2 + 24); \
    const bf16* p3 = klo + gofs + 2048; \
    cp16(base + 3 * FA_ARR, p3); cp16(base + 3 * FA_ARR + 16, p3 + 8); \
    cp16(base + 3 * FA_ARR + 32, p3 + 16); cp16(base + 3 * FA_ARR + 48, p3 + 24); \
} while (0)

    FA_LOAD_KV(0, 0);
    CP_COMMIT();

    float m_r[2] = { -1e30f, -1e30f };
    float l_r[2] = { 0.f, 0.f };
    float o[8][4];
#pragma unroll
    for (int ei = 0; ei < 8; ei++)
#pragma unroll
        for (int r = 0; r < 4; r++) o[ei][r] = 0.f;

    uint32_t qh[4][4], ql[4][4];

    const int a_m = warp * 16 + (grp & 1) * 8 + row_in;
    const int a_k = (grp >> 1) * 8;
    const int b_n = (grp >> 1) * 8 + row_in;
    const int b_k = (grp & 1) * 8;
    const int v_s = (grp & 1) * 8 + row_in;
    const int v_e = (grp >> 1) * 8;

    for (int st = 0; st <= tt; st++) {
        if (st < tt) {
            FA_LOAD_KV(st + 1, (st + 1) & 1);
            CP_COMMIT();
            CP_WAIT(1);
        } else {
            CP_WAIT(0);
        }
        __syncthreads();

        if (st == 0) {
#pragma unroll
            for (int kc = 0; kc < 4; kc++) {
                uint32_t off = (uint32_t)((a_m * QSTR + a_k + kc * 16) * 2);
                ldsm4(qh[kc], smb + off);
                ldsm4(ql[kc], smb + FA_ARR + off);
            }
        }

        const uint32_t kb = smb + FA_BUF0 + (uint32_t)(st & 1) * FA_BUFSZ;

        float sc[8][4];
#pragma unroll
        for (int ni = 0; ni < 8; ni++)
#pragma unroll
            for (int r = 0; r < 4; r++) sc[ni][r] = 0.f;

#pragma unroll
        for (int kc = 0; kc < 4; kc++) {
            uint32_t kh[4][4], kl[4][4];
#pragma unroll
            for (int j = 0; j < 4; j++) {
                uint32_t off = (uint32_t)(((b_n + j * 16) * QSTR + b_k + kc * 16) * 2);
                ldsm4(kh[j], kb + 0 * FA_ARR + off);
                ldsm4(kl[j], kb + 1 * FA_ARR + off);
            }
            // three passes to break accumulator RAW chains
#pragma unroll
            for (int j = 0; j < 4; j++) {
                mma_bf16(sc[2 * j],     qh[kc], kh[j][0], kh[j][1]);
                mma_bf16(sc[2 * j + 1], qh[kc], kh[j][2], kh[j][3]);
            }
#pragma unroll
            for (int j = 0; j < 4; j++) {
                mma_bf16(sc[2 * j],     qh[kc], kl[j][0], kl[j][1]);
                mma_bf16(sc[2 * j + 1], qh[kc], kl[j][2], kl[j][3]);
            }
#pragma unroll
            for (int j = 0; j < 4; j++) {
                mma_bf16(sc[2 * j],     ql[kc], kh[j][0], kh[j][1]);
                mma_bf16(sc[2 * j + 1], ql[kc], kh[j][2], kh[j][3]);
            }
        }

        if (st == tt) {
#pragma unroll
            for (int ni = 0; ni < 8; ni++) {
                int c0 = ni * 8 + 2 * t, c1 = c0 + 1;
                int r0 = warp * 16 + g, r1 = r0 + 8;
                if (c0 > r0) sc[ni][0] = -1e30f;
                if (c1 > r0) sc[ni][1] = -1e30f;
                if (c0 > r1) sc[ni][2] = -1e30f;
                if (c1 > r1) sc[ni][3] = -1e30f;
            }
        }

        float mloc0 = -1e30f, mloc1 = -1e30f;
#pragma unroll
        for (int ni = 0; ni < 8; ni++) {
            mloc0 = fmaxf(mloc0, fmaxf(sc[ni][0], sc[ni][1]));
            mloc1 = fmaxf(mloc1, fmaxf(sc[ni][2], sc[ni][3]));
        }
#pragma unroll
        for (int off = 1; off < 4; off <<= 1) {
            mloc0 = fmaxf(mloc0, __shfl_xor_sync(0xffffffffu, mloc0, off));
            mloc1 = fmaxf(mloc1, __shfl_xor_sync(0xffffffffu, mloc1, off));
        }
        float mnew0 = fmaxf(m_r[0], mloc0);
        float mnew1 = fmaxf(m_r[1], mloc1);
        float scale0 = __expf(m_r[0] - mnew0);
        float scale1 = __expf(m_r[1] - mnew1);
        m_r[0] = mnew0; m_r[1] = mnew1;

        float ls0 = 0.f, ls1 = 0.f;
#pragma unroll
        for (int ni = 0; ni < 8; ni++) {
            sc[ni][0] = __expf(sc[ni][0] - mnew0);
            sc[ni][1] = __expf(sc[ni][1] - mnew0);
            sc[ni][2] = __expf(sc[ni][2] - mnew1);
            sc[ni][3] = __expf(sc[ni][3] - mnew1);
            ls0 += sc[ni][0] + sc[ni][1];
            ls1 += sc[ni][2] + sc[ni][3];
        }
#pragma unroll
        for (int off = 1; off < 4; off <<= 1) {
            ls0 += __shfl_xor_sync(0xffffffffu, ls0, off);
            ls1 += __shfl_xor_sync(0xffffffffu, ls1, off);
        }
        l_r[0] = l_r[0] * scale0 + ls0;
        l_r[1] = l_r[1] * scale1 + ls1;

#pragma unroll
        for (int ei = 0; ei < 8; ei++) {
            o[ei][0] *= scale0; o[ei][1] *= scale0;
            o[ei][2] *= scale1; o[ei][3] *= scale1;
        }

#pragma unroll
        for (int kc = 0; kc < 4; kc++) {
            uint32_t pa_h[4], pa_l[4];
            pa_h[0] = pack_split(sc[2 * kc][0],     sc[2 * kc][1],     pa_l[0]);
            pa_h[1] = pack_split(sc[2 * kc][2],     sc[2 * kc][3],     pa_l[1]);
            pa_h[2] = pack_split(sc[2 * kc + 1][0], sc[2 * kc + 1][1], pa_l[2]);
            pa_h[3] = pack_split(sc[2 * kc + 1][2], sc[2 * kc + 1][3], pa_l[3]);

            uint32_t vh[4][4], vl[4][4];
#pragma unroll
            for (int j = 0; j < 4; j++) {
                uint32_t off = (uint32_t)(((kc * 16 + v_s) * QSTR + j * 16 + v_e) * 2);
                ldsm4t(vh[j], kb + 2 * FA_ARR + off);
                ldsm4t(vl[j], kb + 3 * FA_ARR + off);
            }
            // three passes to break accumulator RAW chains
#pragma unroll
            for (int j = 0; j < 4; j++) {
                mma_bf16(o[2 * j],     pa_h, vh[j][0], vh[j][1]);
                mma_bf16(o[2 * j + 1], pa_h, vh[j][2], vh[j][3]);
            }
#pragma unroll
            for (int j = 0; j < 4; j++) {
                mma_bf16(o[2 * j],     pa_h, vl[j][0], vl[j][1]);
                mma_bf16(o[2 * j + 1], pa_h, vl[j][2], vl[j][3]);
            }
#pragma unroll
            for (int j = 0; j < 4; j++) {
                mma_bf16(o[2 * j],     pa_l, vh[j][0], vh[j][1]);
                mma_bf16(o[2 * j + 1], pa_l, vh[j][2], vh[j][3]);
            }
        }
        __syncthreads();
    }

    const float inv0 = 1.f / l_r[0];
    const float inv1 = 1.f / l_r[1];
    const size_t r0 = (size_t)(b * TT + tt * 64 + warp * 16 + g);
    const size_t r1 = r0 + 8;
#pragma unroll
    for (int ei = 0; ei < 8; ei++) {
        const int col = h * HD + ei * 8 + 2 * t;
        bf16 h0, l0, h1, l1;
        split_bf16(o[ei][0] * inv0, h0, l0);
        split_bf16(o[ei][1] * inv0, h1, l1);
        *(bf162*)(outhi + r0 * DD + col) = bf162(h0, h1);
        *(bf162*)(outlo + r0 * DD + col) = bf162(l0, l1);
        split_bf16(o[ei][2] * inv1, h0, l0);
        split_bf16(o[ei][3] * inv1, h1, l1);
        *(bf162*)(outhi + r1 * DD + col) = bf162(h0, h1);
        *(bf162*)(outlo + r1 * DD + col) = bf162(l0, l1);
    }
#undef FA_LOAD_KV
}

// ---------------- launch ----------------
extern "C" void kernel_launch(void* const* d_in, const int* in_sizes, int n_in,
                              void* d_out, int out_size)
{
    const float* x  = (const float*)d_in[0];
    const float* Wi = (const float*)d_in[1];
    const float* bi = (const float*)d_in[2];
    const float* Wk = (const float*)d_in[3];
    const float* bk = (const float*)d_in[4];
    const float* Wq = (const float*)d_in[5];
    const float* bq = (const float*)d_in[6];
    const float* Wv = (const float*)d_in[7];
    const float* bv = (const float*)d_in[8];
    const float* Wo = (const float*)d_in[9];
    const float* bo = (const float*)d_in[10];
    float* out = (float*)d_out;

    bf16 *p_xhi, *p_xlo, *p_kqvhi, *p_kqvlo, *p_ahi, *p_alo, *p_whi, *p_wlo;
    bf16 *p_wihi, *p_wilo, *p_wchi, *p_wclo;
    float *p_bias, *p_bc, *p_zerob;
    cudaGetSymbolAddress((void**)&p_xhi, g_xhi);
    cudaGetSymbolAddress((void**)&p_xlo, g_xlo);
    cudaGetSymbolAddress((void**)&p_kqvhi, g_kqvhi);
    cudaGetSymbolAddress((void**)&p_kqvlo, g_kqvlo);
    cudaGetSymbolAddress((void**)&p_ahi, g_ahi);
    cudaGetSymbolAddress((void**)&p_alo, g_alo);
    cudaGetSymbolAddress((void**)&p_whi, g_whi);
    cudaGetSymbolAddress((void**)&p_wlo, g_wlo);
    cudaGetSymbolAddress((void**)&p_wihi, g_wihi);
    cudaGetSymbolAddress((void**)&p_wilo, g_wilo);
    cudaGetSymbolAddress((void**)&p_wchi, g_wchi);
    cudaGetSymbolAddress((void**)&p_wclo, g_wclo);
    cudaGetSymbolAddress((void**)&p_bias, g_bias);
    cudaGetSymbolAddress((void**)&p_bc, g_bc);
    cudaGetSymbolAddress((void**)&p_zerob, g_zerob);

    cudaFuncSetAttribute(gemm_bf16x3, cudaFuncAttributeMaxDynamicSharedMemorySize, GEMM_SMEM);
    cudaFuncSetAttribute(flash_mma, cudaFuncAttributeMaxDynamicSharedMemorySize, FLASH_SMEM);

    // prep (all coalesced now)
    prep_bias<<<(NALL + 255) / 256, 256>>>(bi, bk, bq, bv, bo);
    prep_wi<<<(DD * DD / 4 + 255) / 256, 256>>>(Wi);
    {
        dim3 grid(DD / 32, HD / 32, 48);
        prep_wkqv_t<<<grid, dim3(32, 8)>>>(Wk, Wq, Wv);
    }
    {
        dim3 grid(DD / 32, DD / 32);
        prep_wo_t<<<grid, dim3(32, 8)>>>(Wo);
    }
    prep_x<<<(int)(((size_t)MT * DD / 4 + 255) / 256), 256>>>(x);

    // Wc^T[n][din] = sum_k Wkqv_rep[n][k] * Wi[din][k]   (fused Wi@Wkqv)
    {
        dim3 grid(DD / 128, NKQV / 128);
        gemm_bf16x3<<<grid, 256, GEMM_SMEM>>>(
            p_whi + (size_t)DD * DD, p_wlo + (size_t)DD * DD,
            p_wihi, p_wilo, p_zerob,
            nullptr, p_wchi, p_wclo, DD, DD, 1);
    }
    // bc = bi @ Wkqv + bkqv  (warp per output)
    prep_bc<<<(NKQV * 32 + 255) / 256, 256>>>();

    // kqv = x @ Wc^T + bc -> bf16 hi/lo
    {
        dim3 grid(NKQV / 128, MT / 128);
        gemm_bf16x3<<<grid, 256, GEMM_SMEM>>>(p_xhi, p_xlo,
            p_wchi, p_wclo, p_bc,
            nullptr, p_kqvhi, p_kqvlo, DD, NKQV, 1);
    }
    // fused causal attention (tensor cores) -> attn bf16 hi/lo
    {
        dim3 grid(TT / 64, HH, BB);
        flash_mma<<<grid, 128, FLASH_SMEM>>>(p_kqvhi, p_kqvlo, p_ahi, p_alo);
    }
    // out = attn @ Wo + bo -> fp32 to d_out
    {
        dim3 grid(DD / 128, MT / 128);
        gemm_bf16x3<<<grid, 256, GEMM_SMEM>>>(p_ahi, p_alo,
            p_whi + (size_t)(4 * DD) * DD, p_wlo + (size_t)(4 * DD) * DD, p_bias + 4 * DD,
            out, nullptr, nullptr, DD, DD, 0);
    }
}